// round 10
// baseline (speedup 1.0000x reference)
#include <cuda_runtime.h>
#include <math.h>

#define BATCH 2
#define SEQ   2048
#define EMB   4096
#define NH    32
#define NKV   8
#define HD    128
#define MROWS (BATCH*SEQ)     /* 4096 */
#define KVE   (NKV*HD)        /* 1024 */

/* ---------------- scratch (allocation-free: __device__ globals) ---------------- */
__device__ float g_qp[(size_t)MROWS*EMB];    /* 64 MB  q pre/post rope, [b*S+s][h*128+d] */
__device__ float g_kp[(size_t)MROWS*KVE];    /* 16 MB  k                                 */
__device__ float g_vp[(size_t)MROWS*KVE];    /* 16 MB  v                                 */
__device__ float g_attn[(size_t)MROWS*EMB];  /* 64 MB  attention output                  */
__device__ float g_cos[SEQ*64];
__device__ float g_sin[SEQ*64];

/* ---------------- helpers ---------------- */
__device__ __forceinline__ float tf32r(float x) {
    unsigned u;
    asm("cvt.rna.tf32.f32 %0, %1;" : "=r"(u) : "f"(x));
    return __uint_as_float(u);
}

__device__ __forceinline__ void mma8(float* d, const unsigned* a, const unsigned* b) {
    asm volatile(
        "mma.sync.aligned.m16n8k8.row.col.f32.tf32.tf32.f32 "
        "{%0,%1,%2,%3}, {%4,%5,%6,%7}, {%8,%9}, {%0,%1,%2,%3};\n"
        : "+f"(d[0]), "+f"(d[1]), "+f"(d[2]), "+f"(d[3])
        : "r"(a[0]), "r"(a[1]), "r"(a[2]), "r"(a[3]), "r"(b[0]), "r"(b[1]));
}

/* ---------------- RoPE cos/sin table (fp32, mirrors the reference) ---------------- */
__global__ void rope_table_kernel(const int* __restrict__ pos) {
    int i = blockIdx.x * blockDim.x + threadIdx.x;
    if (i >= SEQ * 64) return;
    int s = i >> 6, d = i & 63;
    float e = (float)d * (1.0f / 64.0f);
    float invf = powf(500000.0f, -e);
    float ang = (float)pos[s] * invf;
    float sv, cv;
    sincosf(ang, &sv, &cv);
    g_cos[i] = cv;
    g_sin[i] = sv;
}

/* ---------------- in-place RoPE over [row][h*128+d] ---------------- */
__global__ void rope_apply_kernel(float* __restrict__ buf, int nh) {
    int row = blockIdx.x;              /* 0..MROWS-1 */
    int s = row & (SEQ - 1);
    float* p = buf + (size_t)row * nh * HD;
    for (int idx = threadIdx.x; idx < nh * 64; idx += blockDim.x) {
        int h = idx >> 6, d = idx & 63;
        float x1 = p[h * HD + d];
        float x2 = p[h * HD + d + 64];
        float c  = g_cos[s * 64 + d];
        float sn = g_sin[s * 64 + d];
        p[h * HD + d]      = x1 * c - x2 * sn;
        p[h * HD + d + 64] = x2 * c + x1 * sn;
    }
}

/* ---------------- TF32 GEMM: C[M,N] = A[M,K] * W[N,K]^T ----------------
 * BM=BN=128, BK=32, 256 threads (8 warps: 4(M) x 2(N), warp tile 32x64).
 * Register double-buffered global loads; padded smem -> conflict-free frags. */
__global__ void __launch_bounds__(256, 1)
gemm_tf32_kernel(const float* __restrict__ A, const float* __restrict__ W,
                 float* __restrict__ C, int N, int K)
{
    __shared__ float As[128][36];
    __shared__ float Bs[128][36];

    const int tid  = threadIdx.x;
    const int lane = tid & 31, warp = tid >> 5;
    const int m0 = blockIdx.y * 128, n0 = blockIdx.x * 128;
    const int wm = (warp >> 1) * 32;     /* warp M offset */
    const int wn = (warp & 1) * 64;      /* warp N offset */
    const int g  = lane >> 2, tg = lane & 3;

    const int lr = tid >> 3;             /* 0..31 */
    const int lc = (tid & 7) << 2;       /* 0,4,...,28 */
    const float* Ap = A + (size_t)(m0 + lr) * K + lc;
    const float* Wp = W + (size_t)(n0 + lr) * K + lc;

    float acc[2][8][4];
#pragma unroll
    for (int i = 0; i < 2; i++)
#pragma unroll
        for (int j = 0; j < 8; j++)
#pragma unroll
            for (int l = 0; l < 4; l++) acc[i][j][l] = 0.0f;

    float4 ra[4], rb[4];
#pragma unroll
    for (int i = 0; i < 4; i++) {
        ra[i] = *(const float4*)(Ap + (size_t)i * 32 * K);
        rb[i] = *(const float4*)(Wp + (size_t)i * 32 * K);
    }
#pragma unroll
    for (int i = 0; i < 4; i++) {
        As[lr + i * 32][lc + 0] = tf32r(ra[i].x);
        As[lr + i * 32][lc + 1] = tf32r(ra[i].y);
        As[lr + i * 32][lc + 2] = tf32r(ra[i].z);
        As[lr + i * 32][lc + 3] = tf32r(ra[i].w);
        Bs[lr + i * 32][lc + 0] = tf32r(rb[i].x);
        Bs[lr + i * 32][lc + 1] = tf32r(rb[i].y);
        Bs[lr + i * 32][lc + 2] = tf32r(rb[i].z);
        Bs[lr + i * 32][lc + 3] = tf32r(rb[i].w);
    }
    __syncthreads();

    const int nk = K >> 5;
    for (int kt = 0; kt < nk; ++kt) {
        if (kt + 1 < nk) {
            const float* Ap2 = Ap + (kt + 1) * 32;
            const float* Wp2 = Wp + (kt + 1) * 32;
#pragma unroll
            for (int i = 0; i < 4; i++) {
                ra[i] = *(const float4*)(Ap2 + (size_t)i * 32 * K);
                rb[i] = *(const float4*)(Wp2 + (size_t)i * 32 * K);
            }
        }
#pragma unroll
        for (int ks = 0; ks < 4; ++ks) {
            const int k = ks * 8;
            unsigned af[2][4];
#pragma unroll
            for (int mt = 0; mt < 2; ++mt) {
                int r = wm + mt * 16 + g;
                af[mt][0] = __float_as_uint(As[r][k + tg]);
                af[mt][1] = __float_as_uint(As[r + 8][k + tg]);
                af[mt][2] = __float_as_uint(As[r][k + 4 + tg]);
                af[mt][3] = __float_as_uint(As[r + 8][k + 4 + tg]);
            }
#pragma unroll
            for (int nt = 0; nt < 8; ++nt) {
                int cN = wn + nt * 8 + g;
                unsigned bf[2];
                bf[0] = __float_as_uint(Bs[cN][k + tg]);
                bf[1] = __float_as_uint(Bs[cN][k + 4 + tg]);
                mma8(acc[0][nt], af[0], bf);
                mma8(acc[1][nt], af[1], bf);
            }
        }
        __syncthreads();
        if (kt + 1 < nk) {
#pragma unroll
            for (int i = 0; i < 4; i++) {
                As[lr + i * 32][lc + 0] = tf32r(ra[i].x);
                As[lr + i * 32][lc + 1] = tf32r(ra[i].y);
                As[lr + i * 32][lc + 2] = tf32r(ra[i].z);
                As[lr + i * 32][lc + 3] = tf32r(ra[i].w);
                Bs[lr + i * 32][lc + 0] = tf32r(rb[i].x);
                Bs[lr + i * 32][lc + 1] = tf32r(rb[i].y);
                Bs[lr + i * 32][lc + 2] = tf32r(rb[i].z);
                Bs[lr + i * 32][lc + 3] = tf32r(rb[i].w);
            }
        }
        __syncthreads();
    }

#pragma unroll
    for (int mt = 0; mt < 2; ++mt) {
        int r0 = m0 + wm + mt * 16 + g;
#pragma unroll
        for (int nt = 0; nt < 8; ++nt) {
            int cN = n0 + wn + nt * 8 + 2 * tg;
            *(float2*)(C + (size_t)r0 * N + cN)       = make_float2(acc[mt][nt][0], acc[mt][nt][1]);
            *(float2*)(C + (size_t)(r0 + 8) * N + cN) = make_float2(acc[mt][nt][2], acc[mt][nt][3]);
        }
    }
}

/* ---------------- causal flash attention (GQA), TF32 mma ----------------
 * CTA: 128 q rows of one (b,h). 8 warps x 16 q rows. kv tiles of 64. */
#define ATTN_SMEM_FLOATS (128*132 + 64*132 + 64*132 + 128*68)
#define ATTN_SMEM_BYTES  (ATTN_SMEM_FLOATS * 4)

__global__ void __launch_bounds__(256, 1) attn_kernel() {
    extern __shared__ float sm[];
    float* Qs = sm;                      /* [128][132] */
    float* Ks = Qs + 128 * 132;          /* [64][132]  */
    float* Vs = Ks + 64 * 132;           /* [64][132]  */
    float* Ps = Vs + 64 * 132;           /* [128][68]  */

    const int tid  = threadIdx.x;
    const int lane = tid & 31, warp = tid >> 5;
    const int g = lane >> 2, tg = lane & 3;
    const int qt = blockIdx.x, h = blockIdx.y, b = blockIdx.z;
    const int q0 = qt * 128;
    const int kvh = h >> 2;

    const float* qbase = g_qp + (size_t)b * SEQ * EMB + (size_t)h * HD;
    const float* kbase = g_kp + (size_t)b * SEQ * KVE + (size_t)kvh * HD;
    const float* vbase = g_vp + (size_t)b * SEQ * KVE + (size_t)kvh * HD;

    /* load Q tile (tf32-rounded) */
#pragma unroll
    for (int i = 0; i < 16; i++) {
        int lin = tid + i * 256;
        int r = lin >> 5;
        int c = (lin & 31) << 2;
        float4 v = *(const float4*)(qbase + (size_t)(q0 + r) * EMB + c);
        Qs[r * 132 + c + 0] = tf32r(v.x);
        Qs[r * 132 + c + 1] = tf32r(v.y);
        Qs[r * 132 + c + 2] = tf32r(v.z);
        Qs[r * 132 + c + 3] = tf32r(v.w);
    }

    float o[16][4];
#pragma unroll
    for (int i = 0; i < 16; i++)
#pragma unroll
        for (int j = 0; j < 4; j++) o[i][j] = 0.0f;

    float mi0 = -1e30f, mi1 = -1e30f, li0 = 0.0f, li1 = 0.0f;
    const int rowl0 = warp * 16 + g;
    const float SC = 0.08838834764831845f;  /* 1/sqrt(128) */
    const int nkt = 2 * qt + 2;

    for (int kt = 0; kt < nkt; ++kt) {
        const int k0 = kt * 64;
        __syncthreads();
#pragma unroll
        for (int i = 0; i < 8; i++) {
            int lin = lin = tid + i * 256;
            int r = lin >> 5;
            int c = (lin & 31) << 2;
            float4 kv4 = *(const float4*)(kbase + (size_t)(k0 + r) * KVE + c);
            Ks[r * 132 + c + 0] = tf32r(kv4.x);
            Ks[r * 132 + c + 1] = tf32r(kv4.y);
            Ks[r * 132 + c + 2] = tf32r(kv4.z);
            Ks[r * 132 + c + 3] = tf32r(kv4.w);
            float4 vv4 = *(const float4*)(vbase + (size_t)(k0 + r) * KVE + c);
            Vs[r * 132 + c + 0] = tf32r(vv4.x);
            Vs[r * 132 + c + 1] = tf32r(vv4.y);
            Vs[r * 132 + c + 2] = tf32r(vv4.z);
            Vs[r * 132 + c + 3] = tf32r(vv4.w);
        }
        __syncthreads();

        /* S = Q K^T  (16 x 64 per warp) */
        float sacc[8][4];
#pragma unroll
        for (int i = 0; i < 8; i++)
#pragma unroll
            for (int j = 0; j < 4; j++) sacc[i][j] = 0.0f;

#pragma unroll
        for (int ks = 0; ks < 16; ++ks) {
            const int k = ks * 8;
            unsigned af[4];
            af[0] = __float_as_uint(Qs[rowl0 * 132 + k + tg]);
            af[1] = __float_as_uint(Qs[(rowl0 + 8) * 132 + k + tg]);
            af[2] = __float_as_uint(Qs[rowl0 * 132 + k + 4 + tg]);
            af[3] = __float_as_uint(Qs[(rowl0 + 8) * 132 + k + 4 + tg]);
#pragma unroll
            for (int nt = 0; nt < 8; ++nt) {
                int cN = nt * 8 + g;
                unsigned bf[2];
                bf[0] = __float_as_uint(Ks[cN * 132 + k + tg]);
                bf[1] = __float_as_uint(Ks[cN * 132 + k + 4 + tg]);
                mma8(sacc[nt], af, bf);
            }
        }

        /* scale + causal mask + online softmax update */
        const int qg0 = q0 + rowl0, qg1 = qg0 + 8;
        float rmax0 = -1e30f, rmax1 = -1e30f;
#pragma unroll
        for (int nt = 0; nt < 8; ++nt) {
            int c0 = k0 + nt * 8 + 2 * tg;
            float v0 = sacc[nt][0] * SC; if (c0     > qg0) v0 = -1e30f;
            float v1 = sacc[nt][1] * SC; if (c0 + 1 > qg0) v1 = -1e30f;
            float v2 = sacc[nt][2] * SC; if (c0     > qg1) v2 = -1e30f;
            float v3 = sacc[nt][3] * SC; if (c0 + 1 > qg1) v3 = -1e30f;
            sacc[nt][0] = v0; sacc[nt][1] = v1; sacc[nt][2] = v2; sacc[nt][3] = v3;
            rmax0 = fmaxf(rmax0, fmaxf(v0, v1));
            rmax1 = fmaxf(rmax1, fmaxf(v2, v3));
        }
#pragma unroll
        for (int off = 1; off < 4; off <<= 1) {
            rmax0 = fmaxf(rmax0, __shfl_xor_sync(0xffffffffu, rmax0, off));
            rmax1 = fmaxf(rmax1, __shfl_xor_sync(0xffffffffu, rmax1, off));
        }
        float mn0 = fmaxf(mi0, rmax0), mn1 = fmaxf(mi1, rmax1);
        float al0 = __expf(mi0 - mn0), al1 = __expf(mi1 - mn1);
        float rs0 = 0.0f, rs1 = 0.0f;
#pragma unroll
        for (int nt = 0; nt < 8; ++nt) {
            float p0 = __expf(sacc[nt][0] - mn0);
            float p1 = __expf(sacc[nt][1] - mn0);
            float p2 = __expf(sacc[nt][2] - mn1);
            float p3 = __expf(sacc[nt][3] - mn1);
            rs0 += p0 + p1;
            rs1 += p2 + p3;
            int c = nt * 8 + 2 * tg;
            *(float2*)&Ps[rowl0 * 68 + c]       = make_float2(tf32r(p0), tf32r(p1));
            *(float2*)&Ps[(rowl0 + 8) * 68 + c] = make_float2(tf32r(p2), tf32r(p3));
        }
#pragma unroll
        for (int off = 1; off < 4; off <<= 1) {
            rs0 += __shfl_xor_sync(0xffffffffu, rs0, off);
            rs1 += __shfl_xor_sync(0xffffffffu, rs1, off);
        }
        li0 = li0 * al0 + rs0;
        li1 = li1 * al1 + rs1;
        mi0 = mn0; mi1 = mn1;
#pragma unroll
        for (int nt = 0; nt < 16; ++nt) {
            o[nt][0] *= al0; o[nt][1] *= al0;
            o[nt][2] *= al1; o[nt][3] *= al1;
        }
        __syncwarp();

        /* O += P V  (16 x 128 per warp) */
#pragma unroll
        for (int ks = 0; ks < 8; ++ks) {
            const int k = ks * 8;
            unsigned af[4];
            af[0] = __float_as_uint(Ps[rowl0 * 68 + k + tg]);
            af[1] = __float_as_uint(Ps[(rowl0 + 8) * 68 + k + tg]);
            af[2] = __float_as_uint(Ps[rowl0 * 68 + k + 4 + tg]);
            af[3] = __float_as_uint(Ps[(rowl0 + 8) * 68 + k + 4 + tg]);
#pragma unroll
            for (int nt = 0; nt < 16; ++nt) {
                int cN = nt * 8 + g;
                unsigned bf[2];
                bf[0] = __float_as_uint(Vs[(k + tg) * 132 + cN]);
                bf[1] = __float_as_uint(Vs[(k + 4 + tg) * 132 + cN]);
                mma8(o[nt], af, bf);
            }
        }
    }

    /* epilogue: normalize + write g_attn[b*S+s][h*128+d] */
    float inv0 = 1.0f / li0, inv1 = 1.0f / li1;
    float* obase = g_attn + (size_t)b * SEQ * EMB + (size_t)h * HD;
#pragma unroll
    for (int nt = 0; nt < 16; ++nt) {
        int d = nt * 8 + 2 * tg;
        *(float2*)(obase + (size_t)(q0 + rowl0) * EMB + d) =
            make_float2(o[nt][0] * inv0, o[nt][1] * inv0);
        *(float2*)(obase + (size_t)(q0 + rowl0 + 8) * EMB + d) =
            make_float2(o[nt][2] * inv1, o[nt][3] * inv1);
    }
}

/* ---------------- launch ---------------- */
extern "C" void kernel_launch(void* const* d_in, const int* in_sizes, int n_in,
                              void* d_out, int out_size)
{
    (void)in_sizes; (void)n_in; (void)out_size;
    const float* x   = (const float*)d_in[0];
    const float* wq  = (const float*)d_in[1];
    const float* wk  = (const float*)d_in[2];
    const float* wv  = (const float*)d_in[3];
    const float* wo  = (const float*)d_in[4];
    const int*   pos = (const int*)d_in[5];
    float* out = (float*)d_out;

    float *qp, *kp, *vp, *attn;
    cudaGetSymbolAddress((void**)&qp,   g_qp);
    cudaGetSymbolAddress((void**)&kp,   g_kp);
    cudaGetSymbolAddress((void**)&vp,   g_vp);
    cudaGetSymbolAddress((void**)&attn, g_attn);

    cudaFuncSetAttribute(attn_kernel, cudaFuncAttributeMaxDynamicSharedMemorySize,
                         ATTN_SMEM_BYTES);

    rope_table_kernel<<<(SEQ * 64 + 255) / 256, 256>>>(pos);

    gemm_tf32_kernel<<<dim3(EMB / 128, MROWS / 128), 256>>>(x, wq, qp, EMB, EMB);
    gemm_tf32_kernel<<<dim3(KVE / 128, MROWS / 128), 256>>>(x, wk, kp, KVE, EMB);
    gemm_tf32_kernel<<<dim3(KVE / 128, MROWS / 128), 256>>>(x, wv, vp, KVE, EMB);

    rope_apply_kernel<<<MROWS, 256>>>(qp, NH);
    rope_apply_kernel<<<MROWS, 256>>>(kp, NKV);

    attn_kernel<<<dim3(SEQ / 128, NH, BATCH), 256, ATTN_SMEM_BYTES>>>();

    gemm_tf32_kernel<<<dim3(EMB / 128, MROWS / 128), 256>>>(attn, wo, out, EMB, EMB);
}

// round 11
// speedup vs baseline: 1.0031x; 1.0031x over previous
#include <cuda_runtime.h>
#include <math.h>

#define BATCH 2
#define SEQ   2048
#define EMB   4096
#define NH    32
#define NKV   8
#define HD    128
#define MROWS (BATCH*SEQ)     /* 4096 */
#define KVE   (NKV*HD)        /* 1024 */

/* ---------------- scratch (allocation-free: __device__ globals) ---------------- */
__device__ float g_qp[(size_t)MROWS*EMB];    /* 64 MB  q pre/post rope, [b*S+s][h*128+d] */
__device__ float g_kp[(size_t)MROWS*KVE];    /* 16 MB  k                                 */
__device__ float g_vp[(size_t)MROWS*KVE];    /* 16 MB  v                                 */
__device__ float g_attn[(size_t)MROWS*EMB];  /* 64 MB  attention output                  */
__device__ float g_cos[SEQ*64];
__device__ float g_sin[SEQ*64];

/* ---------------- helpers ---------------- */
__device__ __forceinline__ float tf32r(float x) {
    unsigned u;
    asm("cvt.rna.tf32.f32 %0, %1;" : "=r"(u) : "f"(x));
    return __uint_as_float(u);
}

__device__ __forceinline__ void mma8(float* d, const unsigned* a, const unsigned* b) {
    asm volatile(
        "mma.sync.aligned.m16n8k8.row.col.f32.tf32.tf32.f32 "
        "{%0,%1,%2,%3}, {%4,%5,%6,%7}, {%8,%9}, {%0,%1,%2,%3};\n"
        : "+f"(d[0]), "+f"(d[1]), "+f"(d[2]), "+f"(d[3])
        : "r"(a[0]), "r"(a[1]), "r"(a[2]), "r"(a[3]), "r"(b[0]), "r"(b[1]));
}

/* ---------------- RoPE cos/sin table (fp32, mirrors the reference) ---------------- */
__global__ void rope_table_kernel(const int* __restrict__ pos) {
    int i = blockIdx.x * blockDim.x + threadIdx.x;
    if (i >= SEQ * 64) return;
    int s = i >> 6, d = i & 63;
    float e = (float)d * (1.0f / 64.0f);
    float invf = powf(500000.0f, -e);
    float ang = (float)pos[s] * invf;
    float sv, cv;
    sincosf(ang, &sv, &cv);
    g_cos[i] = cv;
    g_sin[i] = sv;
}

/* ---------------- in-place RoPE over [row][h*128+d] ---------------- */
__global__ void rope_apply_kernel(float* __restrict__ buf, int nh) {
    int row = blockIdx.x;              /* 0..MROWS-1 */
    int s = row & (SEQ - 1);
    float* p = buf + (size_t)row * nh * HD;
    for (int idx = threadIdx.x; idx < nh * 64; idx += blockDim.x) {
        int h = idx >> 6, d = idx & 63;
        float x1 = p[h * HD + d];
        float x2 = p[h * HD + d + 64];
        float c  = g_cos[s * 64 + d];
        float sn = g_sin[s * 64 + d];
        p[h * HD + d]      = x1 * c - x2 * sn;
        p[h * HD + d + 64] = x2 * c + x1 * sn;
    }
}

/* ---------------- TF32 GEMM: C[M,N] = A[M,K] * W[N,K]^T ----------------
 * BM=BN=128, BK=32, 256 threads (8 warps: 4(M) x 2(N), warp tile 32x64).
 * Register double-buffered global loads; padded smem -> conflict-free frags. */
__global__ void __launch_bounds__(256, 1)
gemm_tf32_kernel(const float* __restrict__ A, const float* __restrict__ W,
                 float* __restrict__ C, int N, int K)
{
    __shared__ float As[128][36];
    __shared__ float Bs[128][36];

    const int tid  = threadIdx.x;
    const int lane = tid & 31, warp = tid >> 5;
    const int m0 = blockIdx.y * 128, n0 = blockIdx.x * 128;
    const int wm = (warp >> 1) * 32;     /* warp M offset */
    const int wn = (warp & 1) * 64;      /* warp N offset */
    const int g  = lane >> 2, tg = lane & 3;

    const int lr = tid >> 3;             /* 0..31 */
    const int lc = (tid & 7) << 2;       /* 0,4,...,28 */
    const float* Ap = A + (size_t)(m0 + lr) * K + lc;
    const float* Wp = W + (size_t)(n0 + lr) * K + lc;

    float acc[2][8][4];
#pragma unroll
    for (int i = 0; i < 2; i++)
#pragma unroll
        for (int j = 0; j < 8; j++)
#pragma unroll
            for (int l = 0; l < 4; l++) acc[i][j][l] = 0.0f;

    float4 ra[4], rb[4];
#pragma unroll
    for (int i = 0; i < 4; i++) {
        ra[i] = *(const float4*)(Ap + (size_t)i * 32 * K);
        rb[i] = *(const float4*)(Wp + (size_t)i * 32 * K);
    }
#pragma unroll
    for (int i = 0; i < 4; i++) {
        As[lr + i * 32][lc + 0] = tf32r(ra[i].x);
        As[lr + i * 32][lc + 1] = tf32r(ra[i].y);
        As[lr + i * 32][lc + 2] = tf32r(ra[i].z);
        As[lr + i * 32][lc + 3] = tf32r(ra[i].w);
        Bs[lr + i * 32][lc + 0] = tf32r(rb[i].x);
        Bs[lr + i * 32][lc + 1] = tf32r(rb[i].y);
        Bs[lr + i * 32][lc + 2] = tf32r(rb[i].z);
        Bs[lr + i * 32][lc + 3] = tf32r(rb[i].w);
    }
    __syncthreads();

    const int nk = K >> 5;
    for (int kt = 0; kt < nk; ++kt) {
        if (kt + 1 < nk) {
            const float* Ap2 = Ap + (kt + 1) * 32;
            const float* Wp2 = Wp + (kt + 1) * 32;
#pragma unroll
            for (int i = 0; i < 4; i++) {
                ra[i] = *(const float4*)(Ap2 + (size_t)i * 32 * K);
                rb[i] = *(const float4*)(Wp2 + (size_t)i * 32 * K);
            }
        }
#pragma unroll
        for (int ks = 0; ks < 4; ++ks) {
            const int k = ks * 8;
            unsigned af[2][4];
#pragma unroll
            for (int mt = 0; mt < 2; ++mt) {
                int r = wm + mt * 16 + g;
                af[mt][0] = __float_as_uint(As[r][k + tg]);
                af[mt][1] = __float_as_uint(As[r + 8][k + tg]);
                af[mt][2] = __float_as_uint(As[r][k + 4 + tg]);
                af[mt][3] = __float_as_uint(As[r + 8][k + 4 + tg]);
            }
#pragma unroll
            for (int nt = 0; nt < 8; ++nt) {
                int cN = wn + nt * 8 + g;
                unsigned bf[2];
                bf[0] = __float_as_uint(Bs[cN][k + tg]);
                bf[1] = __float_as_uint(Bs[cN][k + 4 + tg]);
                mma8(acc[0][nt], af[0], bf);
                mma8(acc[1][nt], af[1], bf);
            }
        }
        __syncthreads();
        if (kt + 1 < nk) {
#pragma unroll
            for (int i = 0; i < 4; i++) {
                As[lr + i * 32][lc + 0] = tf32r(ra[i].x);
                As[lr + i * 32][lc + 1] = tf32r(ra[i].y);
                As[lr + i * 32][lc + 2] = tf32r(ra[i].z);
                As[lr + i * 32][lc + 3] = tf32r(ra[i].w);
                Bs[lr + i * 32][lc + 0] = tf32r(rb[i].x);
                Bs[lr + i * 32][lc + 1] = tf32r(rb[i].y);
                Bs[lr + i * 32][lc + 2] = tf32r(rb[i].z);
                Bs[lr + i * 32][lc + 3] = tf32r(rb[i].w);
            }
        }
        __syncthreads();
    }

#pragma unroll
    for (int mt = 0; mt < 2; ++mt) {
        int r0 = m0 + wm + mt * 16 + g;
#pragma unroll
        for (int nt = 0; nt < 8; ++nt) {
            int cN = n0 + wn + nt * 8 + 2 * tg;
            *(float2*)(C + (size_t)r0 * N + cN)       = make_float2(acc[mt][nt][0], acc[mt][nt][1]);
            *(float2*)(C + (size_t)(r0 + 8) * N + cN) = make_float2(acc[mt][nt][2], acc[mt][nt][3]);
        }
    }
}

/* ---------------- causal flash attention (GQA), TF32 mma ----------------
 * CTA: 128 q rows of one (b,h). 8 warps x 16 q rows. kv tiles of 64. */
#define ATTN_SMEM_FLOATS (128*132 + 64*132 + 64*132 + 128*68)
#define ATTN_SMEM_BYTES  (ATTN_SMEM_FLOATS * 4)

__global__ void __launch_bounds__(256, 1) attn_kernel() {
    extern __shared__ float sm[];
    float* Qs = sm;                      /* [128][132] */
    float* Ks = Qs + 128 * 132;          /* [64][132]  */
    float* Vs = Ks + 64 * 132;           /* [64][132]  */
    float* Ps = Vs + 64 * 132;           /* [128][68]  */

    const int tid  = threadIdx.x;
    const int lane = tid & 31, warp = tid >> 5;
    const int g = lane >> 2, tg = lane & 3;
    const int qt = blockIdx.x, h = blockIdx.y, b = blockIdx.z;
    const int q0 = qt * 128;
    const int kvh = h >> 2;

    const float* qbase = g_qp + (size_t)b * SEQ * EMB + (size_t)h * HD;
    const float* kbase = g_kp + (size_t)b * SEQ * KVE + (size_t)kvh * HD;
    const float* vbase = g_vp + (size_t)b * SEQ * KVE + (size_t)kvh * HD;

    /* load Q tile (tf32-rounded) */
#pragma unroll
    for (int i = 0; i < 16; i++) {
        int lin = tid + i * 256;
        int r = lin >> 5;
        int c = (lin & 31) << 2;
        float4 v = *(const float4*)(qbase + (size_t)(q0 + r) * EMB + c);
        Qs[r * 132 + c + 0] = tf32r(v.x);
        Qs[r * 132 + c + 1] = tf32r(v.y);
        Qs[r * 132 + c + 2] = tf32r(v.z);
        Qs[r * 132 + c + 3] = tf32r(v.w);
    }

    float o[16][4];
#pragma unroll
    for (int i = 0; i < 16; i++)
#pragma unroll
        for (int j = 0; j < 4; j++) o[i][j] = 0.0f;

    float mi0 = -1e30f, mi1 = -1e30f, li0 = 0.0f, li1 = 0.0f;
    const int rowl0 = warp * 16 + g;
    const float SC = 0.08838834764831845f;  /* 1/sqrt(128) */
    const int nkt = 2 * qt + 2;

    for (int kt = 0; kt < nkt; ++kt) {
        const int k0 = kt * 64;
        __syncthreads();
#pragma unroll
        for (int i = 0; i < 8; i++) {
            int lin = lin = tid + i * 256;
            int r = lin >> 5;
            int c = (lin & 31) << 2;
            float4 kv4 = *(const float4*)(kbase + (size_t)(k0 + r) * KVE + c);
            Ks[r * 132 + c + 0] = tf32r(kv4.x);
            Ks[r * 132 + c + 1] = tf32r(kv4.y);
            Ks[r * 132 + c + 2] = tf32r(kv4.z);
            Ks[r * 132 + c + 3] = tf32r(kv4.w);
            float4 vv4 = *(const float4*)(vbase + (size_t)(k0 + r) * KVE + c);
            Vs[r * 132 + c + 0] = tf32r(vv4.x);
            Vs[r * 132 + c + 1] = tf32r(vv4.y);
            Vs[r * 132 + c + 2] = tf32r(vv4.z);
            Vs[r * 132 + c + 3] = tf32r(vv4.w);
        }
        __syncthreads();

        /* S = Q K^T  (16 x 64 per warp) */
        float sacc[8][4];
#pragma unroll
        for (int i = 0; i < 8; i++)
#pragma unroll
            for (int j = 0; j < 4; j++) sacc[i][j] = 0.0f;

#pragma unroll
        for (int ks = 0; ks < 16; ++ks) {
            const int k = ks * 8;
            unsigned af[4];
            af[0] = __float_as_uint(Qs[rowl0 * 132 + k + tg]);
            af[1] = __float_as_uint(Qs[(rowl0 + 8) * 132 + k + tg]);
            af[2] = __float_as_uint(Qs[rowl0 * 132 + k + 4 + tg]);
            af[3] = __float_as_uint(Qs[(rowl0 + 8) * 132 + k + 4 + tg]);
#pragma unroll
            for (int nt = 0; nt < 8; ++nt) {
                int cN = nt * 8 + g;
                unsigned bf[2];
                bf[0] = __float_as_uint(Ks[cN * 132 + k + tg]);
                bf[1] = __float_as_uint(Ks[cN * 132 + k + 4 + tg]);
                mma8(sacc[nt], af, bf);
            }
        }

        /* scale + causal mask + online softmax update */
        const int qg0 = q0 + rowl0, qg1 = qg0 + 8;
        float rmax0 = -1e30f, rmax1 = -1e30f;
#pragma unroll
        for (int nt = 0; nt < 8; ++nt) {
            int c0 = k0 + nt * 8 + 2 * tg;
            float v0 = sacc[nt][0] * SC; if (c0     > qg0) v0 = -1e30f;
            float v1 = sacc[nt][1] * SC; if (c0 + 1 > qg0) v1 = -1e30f;
            float v2 = sacc[nt][2] * SC; if (c0     > qg1) v2 = -1e30f;
            float v3 = sacc[nt][3] * SC; if (c0 + 1 > qg1) v3 = -1e30f;
            sacc[nt][0] = v0; sacc[nt][1] = v1; sacc[nt][2] = v2; sacc[nt][3] = v3;
            rmax0 = fmaxf(rmax0, fmaxf(v0, v1));
            rmax1 = fmaxf(rmax1, fmaxf(v2, v3));
        }
#pragma unroll
        for (int off = 1; off < 4; off <<= 1) {
            rmax0 = fmaxf(rmax0, __shfl_xor_sync(0xffffffffu, rmax0, off));
            rmax1 = fmaxf(rmax1, __shfl_xor_sync(0xffffffffu, rmax1, off));
        }
        float mn0 = fmaxf(mi0, rmax0), mn1 = fmaxf(mi1, rmax1);
        float al0 = __expf(mi0 - mn0), al1 = __expf(mi1 - mn1);
        float rs0 = 0.0f, rs1 = 0.0f;
#pragma unroll
        for (int nt = 0; nt < 8; ++nt) {
            float p0 = __expf(sacc[nt][0] - mn0);
            float p1 = __expf(sacc[nt][1] - mn0);
            float p2 = __expf(sacc[nt][2] - mn1);
            float p3 = __expf(sacc[nt][3] - mn1);
            rs0 += p0 + p1;
            rs1 += p2 + p3;
            int c = nt * 8 + 2 * tg;
            *(float2*)&Ps[rowl0 * 68 + c]       = make_float2(tf32r(p0), tf32r(p1));
            *(float2*)&Ps[(rowl0 + 8) * 68 + c] = make_float2(tf32r(p2), tf32r(p3));
        }
#pragma unroll
        for (int off = 1; off < 4; off <<= 1) {
            rs0 += __shfl_xor_sync(0xffffffffu, rs0, off);
            rs1 += __shfl_xor_sync(0xffffffffu, rs1, off);
        }
        li0 = li0 * al0 + rs0;
        li1 = li1 * al1 + rs1;
        mi0 = mn0; mi1 = mn1;
#pragma unroll
        for (int nt = 0; nt < 16; ++nt) {
            o[nt][0] *= al0; o[nt][1] *= al0;
            o[nt][2] *= al1; o[nt][3] *= al1;
        }
        __syncwarp();

        /* O += P V  (16 x 128 per warp) */
#pragma unroll
        for (int ks = 0; ks < 8; ++ks) {
            const int k = ks * 8;
            unsigned af[4];
            af[0] = __float_as_uint(Ps[rowl0 * 68 + k + tg]);
            af[1] = __float_as_uint(Ps[(rowl0 + 8) * 68 + k + tg]);
            af[2] = __float_as_uint(Ps[rowl0 * 68 + k + 4 + tg]);
            af[3] = __float_as_uint(Ps[(rowl0 + 8) * 68 + k + 4 + tg]);
#pragma unroll
            for (int nt = 0; nt < 16; ++nt) {
                int cN = nt * 8 + g;
                unsigned bf[2];
                bf[0] = __float_as_uint(Vs[(k + tg) * 132 + cN]);
                bf[1] = __float_as_uint(Vs[(k + 4 + tg) * 132 + cN]);
                mma8(o[nt], af, bf);
            }
        }
    }

    /* epilogue: normalize + write g_attn[b*S+s][h*128+d] */
    float inv0 = 1.0f / li0, inv1 = 1.0f / li1;
    float* obase = g_attn + (size_t)b * SEQ * EMB + (size_t)h * HD;
#pragma unroll
    for (int nt = 0; nt < 16; ++nt) {
        int d = nt * 8 + 2 * tg;
        *(float2*)(obase + (size_t)(q0 + rowl0) * EMB + d) =
            make_float2(o[nt][0] * inv0, o[nt][1] * inv0);
        *(float2*)(obase + (size_t)(q0 + rowl0 + 8) * EMB + d) =
            make_float2(o[nt][2] * inv1, o[nt][3] * inv1);
    }
}

/* ---------------- launch ---------------- */
extern "C" void kernel_launch(void* const* d_in, const int* in_sizes, int n_in,
                              void* d_out, int out_size)
{
    (void)in_sizes; (void)n_in; (void)out_size;
    const float* x   = (const float*)d_in[0];
    const float* wq  = (const float*)d_in[1];
    const float* wk  = (const float*)d_in[2];
    const float* wv  = (const float*)d_in[3];
    const float* wo  = (const float*)d_in[4];
    const int*   pos = (const int*)d_in[5];
    float* out = (float*)d_out;

    float *qp, *kp, *vp, *attn;
    cudaGetSymbolAddress((void**)&qp,   g_qp);
    cudaGetSymbolAddress((void**)&kp,   g_kp);
    cudaGetSymbolAddress((void**)&vp,   g_vp);
    cudaGetSymbolAddress((void**)&attn, g_attn);

    cudaFuncSetAttribute(attn_kernel, cudaFuncAttributeMaxDynamicSharedMemorySize,
                         ATTN_SMEM_BYTES);

    rope_table_kernel<<<(SEQ * 64 + 255) / 256, 256>>>(pos);

    gemm_tf32_kernel<<<dim3(EMB / 128, MROWS / 128), 256>>>(x, wq, qp, EMB, EMB);
    gemm_tf32_kernel<<<dim3(KVE / 128, MROWS / 128), 256>>>(x, wk, kp, KVE, EMB);
    gemm_tf32_kernel<<<dim3(KVE / 128, MROWS / 128), 256>>>(x, wv, vp, KVE, EMB);

    rope_apply_kernel<<<MROWS, 256>>>(qp, NH);
    rope_apply_kernel<<<MROWS, 256>>>(kp, NKV);

    attn_kernel<<<dim3(SEQ / 128, NH, BATCH), 256, ATTN_SMEM_BYTES>>>();

    gemm_tf32_kernel<<<dim3(EMB / 128, MROWS / 128), 256>>>(attn, wo, out, EMB, EMB);
}

// round 14
// speedup vs baseline: 1.1919x; 1.1883x over previous
#include <cuda_runtime.h>
#include <math.h>
#include <cstdint>

#define BATCH 2
#define SEQ   2048
#define EMB   4096
#define NH    32
#define NKV   8
#define HD    128
#define MROWS (BATCH*SEQ)     /* 4096 */
#define KVE   (NKV*HD)        /* 1024 */
#define GK    4096            /* K dim of every GEMM in this block */

/* ---------------- scratch (allocation-free: __device__ globals) ---------------- */
__device__ float g_qp[(size_t)MROWS*EMB];    /* 64 MB */
__device__ float g_kp[(size_t)MROWS*KVE];    /* 16 MB */
__device__ float g_vp[(size_t)MROWS*KVE];    /* 16 MB */
__device__ float g_attn[(size_t)MROWS*EMB];  /* 64 MB, written tf32-rounded */
__device__ float g_xr[(size_t)MROWS*EMB];    /* 64 MB, tf32-rounded x */
__device__ float g_wqr[(size_t)EMB*EMB];     /* 64 MB */
__device__ float g_wkr[(size_t)KVE*EMB];     /* 16 MB */
__device__ float g_wvr[(size_t)KVE*EMB];     /* 16 MB */
__device__ float g_wor[(size_t)EMB*EMB];     /* 64 MB */
__device__ float g_cos[SEQ*64];
__device__ float g_sin[SEQ*64];

/* ---------------- helpers ---------------- */
__device__ __forceinline__ float tf32r(float x) {
    unsigned u;
    asm("cvt.rna.tf32.f32 %0, %1;" : "=r"(u) : "f"(x));
    return __uint_as_float(u);
}

__device__ __forceinline__ void mma8(float* d, const unsigned* a, const unsigned* b) {
    asm volatile(
        "mma.sync.aligned.m16n8k8.row.col.f32.tf32.tf32.f32 "
        "{%0,%1,%2,%3}, {%4,%5,%6,%7}, {%8,%9}, {%0,%1,%2,%3};\n"
        : "+f"(d[0]), "+f"(d[1]), "+f"(d[2]), "+f"(d[3])
        : "r"(a[0]), "r"(a[1]), "r"(a[2]), "r"(a[3]), "r"(b[0]), "r"(b[1]));
}

__device__ __forceinline__ uint32_t su32(const void* p) {
    uint32_t a;
    asm("{ .reg .u64 t; cvta.to.shared.u64 t, %1; cvt.u32.u64 %0, t; }"
        : "=r"(a) : "l"(p));
    return a;
}

__device__ __forceinline__ void cpa16(uint32_t dst, const void* src) {
    asm volatile("cp.async.cg.shared.global [%0], [%1], 16;"
                 :: "r"(dst), "l"(src) : "memory");
}
#define CP_COMMIT() asm volatile("cp.async.commit_group;" ::: "memory")
#define CP_WAIT2()  asm volatile("cp.async.wait_group 2;"  ::: "memory")

#define LDSM4(r0, r1, r2, r3, addr) \
    asm volatile("ldmatrix.sync.aligned.m8n8.x4.shared.b16 {%0,%1,%2,%3}, [%4];" \
                 : "=r"(r0), "=r"(r1), "=r"(r2), "=r"(r3) : "r"(addr))

/* ---------------- tf32 rounding pass (x + weights) ---------------- */
__global__ void round_copy_kernel(const float* __restrict__ src,
                                  float* __restrict__ dst, int n4) {
    int i = blockIdx.x * blockDim.x + threadIdx.x;
    if (i >= n4) return;
    float4 v = ((const float4*)src)[i];
    v.x = tf32r(v.x); v.y = tf32r(v.y); v.z = tf32r(v.z); v.w = tf32r(v.w);
    ((float4*)dst)[i] = v;
}

/* ---------------- RoPE cos/sin table ---------------- */
__global__ void rope_table_kernel(const int* __restrict__ pos) {
    int i = blockIdx.x * blockDim.x + threadIdx.x;
    if (i >= SEQ * 64) return;
    int s = i >> 6, d = i & 63;
    float e = (float)d * (1.0f / 64.0f);
    float invf = powf(500000.0f, -e);
    float ang = (float)pos[s] * invf;
    float sv, cv;
    sincosf(ang, &sv, &cv);
    g_cos[i] = cv;
    g_sin[i] = sv;
}

/* ---------------- in-place RoPE over [row][h*128+d] ---------------- */
__global__ void rope_apply_kernel(float* __restrict__ buf, int nh) {
    int row = blockIdx.x;
    int s = row & (SEQ - 1);
    float* p = buf + (size_t)row * nh * HD;
    for (int idx = threadIdx.x; idx < nh * 64; idx += blockDim.x) {
        int h = idx >> 6, d = idx & 63;
        float x1 = p[h * HD + d];
        float x2 = p[h * HD + d + 64];
        float c  = g_cos[s * 64 + d];
        float sn = g_sin[s * 64 + d];
        p[h * HD + d]      = x1 * c - x2 * sn;
        p[h * HD + d + 64] = x2 * c + x1 * sn;
    }
}

/* ================= TF32 GEMM v2: C[M,Ntot] = A[M,4096] * W[Ntot,4096]^T =================
 * Inputs pre-rounded to tf32. CTA tile 128x128, BK=32, 4-stage cp.async pipeline,
 * ldmatrix fragment loads, 8 warps (4M x 2N), warp tile 32x64.
 * Stage: A tile 128rows x 128B at +0, B tile 128rows x 128B at +16384 (32KB/stage). */
#define G_STAGE 32768
#define GEMM_DYN (4*G_STAGE)

__device__ __forceinline__ void load_chunk_async(
    const float* __restrict__ A, const float* __restrict__ W,
    int m0, int n0, int kk, uint32_t sstage, int tid)
{
#pragma unroll
    for (int it = 0; it < 8; ++it) {
        int lin = tid + it * 256;
        int r = lin >> 3, c = lin & 7;
        const float* src;
        int off;
        if (it < 4) {
            src = A + (size_t)(m0 + r) * GK + (kk + c * 4);
            off = r * 128 + c * 16;
        } else {
            src = W + (size_t)(n0 + r - 128) * GK + (kk + c * 4);
            off = 16384 + (r - 128) * 128 + c * 16;
        }
        off ^= ((off >> 3) & 0x70);              /* 128B xor swizzle */
        cpa16(sstage + off, src);
    }
}

__global__ void __launch_bounds__(256, 1)
gemm_tf32_v2(const float* __restrict__ A, const float* __restrict__ W,
             float* __restrict__ C, int Ntot)
{
    extern __shared__ char dsm[];
    const uint32_t s0 = su32(dsm);

    const int tid  = threadIdx.x;
    const int lane = tid & 31, warp = tid >> 5;
    const int m0 = blockIdx.y * 128, n0 = blockIdx.x * 128;
    const int wm = (warp >> 1) * 32;
    const int wn = (warp & 1) * 64;
    const int g  = lane >> 2, tg = lane & 3;

    /* per-lane ldmatrix addressing (stage-relative) */
    const uint32_t xorv = (uint32_t)(lane & 7) << 4;
    const uint32_t aOff = (uint32_t)(wm + (lane & 15)) * 128;       /* + mt*2048 */
    const uint32_t aHi  = (uint32_t)(lane >> 4) * 16;
    const uint32_t bOff = 16384u +
        (uint32_t)(wn + (lane & 7) + ((lane >> 4) & 1) * 8) * 128;  /* + p*2048 */
    const uint32_t bHi  = (uint32_t)((lane >> 3) & 1) * 16;

    float acc[2][8][4];
#pragma unroll
    for (int i = 0; i < 2; i++)
#pragma unroll
        for (int j = 0; j < 8; j++)
#pragma unroll
            for (int l = 0; l < 4; l++) acc[i][j][l] = 0.0f;

    /* preload 3 stages */
    load_chunk_async(A, W, m0, n0, 0,  s0,              tid); CP_COMMIT();
    load_chunk_async(A, W, m0, n0, 32, s0 + G_STAGE,    tid); CP_COMMIT();
    load_chunk_async(A, W, m0, n0, 64, s0 + 2*G_STAGE,  tid); CP_COMMIT();

    const int n = GK / 32;                       /* 128 chunks */
    for (int i = 0; i < n; ++i) {
        CP_WAIT2();
        __syncthreads();

        if (i + 3 < n)
            load_chunk_async(A, W, m0, n0, (i + 3) * 32,
                             s0 + (uint32_t)((i + 3) & 3) * G_STAGE, tid);
        CP_COMMIT();

        const uint32_t sb = s0 + (uint32_t)(i & 3) * G_STAGE;
#pragma unroll
        for (int ks = 0; ks < 4; ++ks) {
            const uint32_t ka = ((uint32_t)(ks * 32) + aHi) ^ xorv;
            const uint32_t kb = ((uint32_t)(ks * 32) + bHi) ^ xorv;
            unsigned a0[4], a1[4], bf[16];
            LDSM4(a0[0], a0[1], a0[2], a0[3], sb + aOff + ka);
            LDSM4(a1[0], a1[1], a1[2], a1[3], sb + aOff + 2048 + ka);
            LDSM4(bf[0],  bf[1],  bf[2],  bf[3],  sb + bOff + kb);
            LDSM4(bf[4],  bf[5],  bf[6],  bf[7],  sb + bOff + 2048 + kb);
            LDSM4(bf[8],  bf[9],  bf[10], bf[11], sb + bOff + 4096 + kb);
            LDSM4(bf[12], bf[13], bf[14], bf[15], sb + bOff + 6144 + kb);
#pragma unroll
            for (int nt = 0; nt < 8; ++nt) {
                mma8(acc[0][nt], a0, &bf[nt * 2]);
                mma8(acc[1][nt], a1, &bf[nt * 2]);
            }
        }
        __syncthreads();
    }

    /* epilogue */
#pragma unroll
    for (int mt = 0; mt < 2; ++mt) {
        int r0 = m0 + wm + mt * 16 + g;
#pragma unroll
        for (int nt = 0; nt < 8; ++nt) {
            int cN = n0 + wn + nt * 8 + 2 * tg;
            *(float2*)(C + (size_t)r0 * Ntot + cN)       = make_float2(acc[mt][nt][0], acc[mt][nt][1]);
            *(float2*)(C + (size_t)(r0 + 8) * Ntot + cN) = make_float2(acc[mt][nt][2], acc[mt][nt][3]);
        }
    }
}

/* ---------------- causal flash attention (GQA), TF32 mma ---------------- */
#define ATTN_SMEM_FLOATS (128*132 + 64*132 + 64*132 + 128*68)
#define ATTN_SMEM_BYTES  (ATTN_SMEM_FLOATS * 4)

__global__ void __launch_bounds__(256, 1) attn_kernel() {
    extern __shared__ float sm[];
    float* Qs = sm;                      /* [128][132] */
    float* Ks = Qs + 128 * 132;          /* [64][132]  */
    float* Vs = Ks + 64 * 132;           /* [64][132]  */
    float* Ps = Vs + 64 * 132;           /* [128][68]  */

    const int tid  = threadIdx.x;
    const int lane = tid & 31, warp = tid >> 5;
    const int g = lane >> 2, tg = lane & 3;
    const int qt = blockIdx.x, h = blockIdx.y, b = blockIdx.z;
    const int q0 = qt * 128;
    const int kvh = h >> 2;

    const float* qbase = g_qp + (size_t)b * SEQ * EMB + (size_t)h * HD;
    const float* kbase = g_kp + (size_t)b * SEQ * KVE + (size_t)kvh * HD;
    const float* vbase = g_vp + (size_t)b * SEQ * KVE + (size_t)kvh * HD;

#pragma unroll
    for (int i = 0; i < 16; i++) {
        int lin = tid + i * 256;
        int r = lin >> 5;
        int c = (lin & 31) << 2;
        float4 v = *(const float4*)(qbase + (size_t)(q0 + r) * EMB + c);
        Qs[r * 132 + c + 0] = tf32r(v.x);
        Qs[r * 132 + c + 1] = tf32r(v.y);
        Qs[r * 132 + c + 2] = tf32r(v.z);
        Qs[r * 132 + c + 3] = tf32r(v.w);
    }

    float o[16][4];
#pragma unroll
    for (int i = 0; i < 16; i++)
#pragma unroll
        for (int j = 0; j < 4; j++) o[i][j] = 0.0f;

    float mi0 = -1e30f, mi1 = -1e30f, li0 = 0.0f, li1 = 0.0f;
    const int rowl0 = warp * 16 + g;
    const float SC = 0.08838834764831845f;
    const int nkt = 2 * qt + 2;

    for (int kt = 0; kt < nkt; ++kt) {
        const int k0 = kt * 64;
        __syncthreads();
#pragma unroll
        for (int i = 0; i < 8; i++) {
            int lin = tid + i * 256;
            int r = lin >> 5;
            int c = (lin & 31) << 2;
            float4 kv4 = *(const float4*)(kbase + (size_t)(k0 + r) * KVE + c);
            Ks[r * 132 + c + 0] = tf32r(kv4.x);
            Ks[r * 132 + c + 1] = tf32r(kv4.y);
            Ks[r * 132 + c + 2] = tf32r(kv4.z);
            Ks[r * 132 + c + 3] = tf32r(kv4.w);
            float4 vv4 = *(const float4*)(vbase + (size_t)(k0 + r) * KVE + c);
            Vs[r * 132 + c + 0] = tf32r(vv4.x);
            Vs[r * 132 + c + 1] = tf32r(vv4.y);
            Vs[r * 132 + c + 2] = tf32r(vv4.z);
            Vs[r * 132 + c + 3] = tf32r(vv4.w);
        }
        __syncthreads();

        float sacc[8][4];
#pragma unroll
        for (int i = 0; i < 8; i++)
#pragma unroll
            for (int j = 0; j < 4; j++) sacc[i][j] = 0.0f;

#pragma unroll
        for (int ks = 0; ks < 16; ++ks) {
            const int k = ks * 8;
            unsigned af[4];
            af[0] = __float_as_uint(Qs[rowl0 * 132 + k + tg]);
            af[1] = __float_as_uint(Qs[(rowl0 + 8) * 132 + k + tg]);
            af[2] = __float_as_uint(Qs[rowl0 * 132 + k + 4 + tg]);
            af[3] = __float_as_uint(Qs[(rowl0 + 8) * 132 + k + 4 + tg]);
#pragma unroll
            for (int nt = 0; nt < 8; ++nt) {
                int cN = nt * 8 + g;
                unsigned bf[2];
                bf[0] = __float_as_uint(Ks[cN * 132 + k + tg]);
                bf[1] = __float_as_uint(Ks[cN * 132 + k + 4 + tg]);
                mma8(sacc[nt], af, bf);
            }
        }

        const int qg0 = q0 + rowl0, qg1 = qg0 + 8;
        float rmax0 = -1e30f, rmax1 = -1e30f;
#pragma unroll
        for (int nt = 0; nt < 8; ++nt) {
            int c0 = k0 + nt * 8 + 2 * tg;
            float v0 = sacc[nt][0] * SC; if (c0     > qg0) v0 = -1e30f;
            float v1 = sacc[nt][1] * SC; if (c0 + 1 > qg0) v1 = -1e30f;
            float v2 = sacc[nt][2] * SC; if (c0     > qg1) v2 = -1e30f;
            float v3 = sacc[nt][3] * SC; if (c0 + 1 > qg1) v3 = -1e30f;
            sacc[nt][0] = v0; sacc[nt][1] = v1; sacc[nt][2] = v2; sacc[nt][3] = v3;
            rmax0 = fmaxf(rmax0, fmaxf(v0, v1));
            rmax1 = fmaxf(rmax1, fmaxf(v2, v3));
        }
#pragma unroll
        for (int off = 1; off < 4; off <<= 1) {
            rmax0 = fmaxf(rmax0, __shfl_xor_sync(0xffffffffu, rmax0, off));
            rmax1 = fmaxf(rmax1, __shfl_xor_sync(0xffffffffu, rmax1, off));
        }
        float mn0 = fmaxf(mi0, rmax0), mn1 = fmaxf(mi1, rmax1);
        float al0 = __expf(mi0 - mn0), al1 = __expf(mi1 - mn1);
        float rs0 = 0.0f, rs1 = 0.0f;
#pragma unroll
        for (int nt = 0; nt < 8; ++nt) {
            float p0 = __expf(sacc[nt][0] - mn0);
            float p1 = __expf(sacc[nt][1] - mn0);
            float p2 = __expf(sacc[nt][2] - mn1);
            float p3 = __expf(sacc[nt][3] - mn1);
            rs0 += p0 + p1;
            rs1 += p2 + p3;
            int c = nt * 8 + 2 * tg;
            *(float2*)&Ps[rowl0 * 68 + c]       = make_float2(tf32r(p0), tf32r(p1));
            *(float2*)&Ps[(rowl0 + 8) * 68 + c] = make_float2(tf32r(p2), tf32r(p3));
        }
#pragma unroll
        for (int off = 1; off < 4; off <<= 1) {
            rs0 += __shfl_xor_sync(0xffffffffu, rs0, off);
            rs1 += __shfl_xor_sync(0xffffffffu, rs1, off);
        }
        li0 = li0 * al0 + rs0;
        li1 = li1 * al1 + rs1;
        mi0 = mn0; mi1 = mn1;
#pragma unroll
        for (int nt = 0; nt < 16; ++nt) {
            o[nt][0] *= al0; o[nt][1] *= al0;
            o[nt][2] *= al1; o[nt][3] *= al1;
        }
        __syncwarp();

#pragma unroll
        for (int ks = 0; ks < 8; ++ks) {
            const int k = ks * 8;
            unsigned af[4];
            af[0] = __float_as_uint(Ps[rowl0 * 68 + k + tg]);
            af[1] = __float_as_uint(Ps[(rowl0 + 8) * 68 + k + tg]);
            af[2] = __float_as_uint(Ps[rowl0 * 68 + k + 4 + tg]);
            af[3] = __float_as_uint(Ps[(rowl0 + 8) * 68 + k + 4 + tg]);
#pragma unroll
            for (int nt = 0; nt < 16; ++nt) {
                int cN = nt * 8 + g;
                unsigned bf[2];
                bf[0] = __float_as_uint(Vs[(k + tg) * 132 + cN]);
                bf[1] = __float_as_uint(Vs[(k + 4 + tg) * 132 + cN]);
                mma8(o[nt], af, bf);
            }
        }
    }

    /* epilogue: normalize + tf32-round (feeds O-proj as pre-rounded A) */
    float inv0 = 1.0f / li0, inv1 = 1.0f / li1;
    float* obase = g_attn + (size_t)b * SEQ * EMB + (size_t)h * HD;
#pragma unroll
    for (int nt = 0; nt < 16; ++nt) {
        int d = nt * 8 + 2 * tg;
        *(float2*)(obase + (size_t)(q0 + rowl0) * EMB + d) =
            make_float2(tf32r(o[nt][0] * inv0), tf32r(o[nt][1] * inv0));
        *(float2*)(obase + (size_t)(q0 + rowl0 + 8) * EMB + d) =
            make_float2(tf32r(o[nt][2] * inv1), tf32r(o[nt][3] * inv1));
    }
}

/* ---------------- launch ---------------- */
extern "C" void kernel_launch(void* const* d_in, const int* in_sizes, int n_in,
                              void* d_out, int out_size)
{
    (void)in_sizes; (void)n_in; (void)out_size;
    const float* x   = (const float*)d_in[0];
    const float* wq  = (const float*)d_in[1];
    const float* wk  = (const float*)d_in[2];
    const float* wv  = (const float*)d_in[3];
    const float* wo  = (const float*)d_in[4];
    const int*   pos = (const int*)d_in[5];
    float* out = (float*)d_out;

    float *qp, *kp, *vp, *attn, *xr, *wqr, *wkr, *wvr, *wor;
    cudaGetSymbolAddress((void**)&qp,   g_qp);
    cudaGetSymbolAddress((void**)&kp,   g_kp);
    cudaGetSymbolAddress((void**)&vp,   g_vp);
    cudaGetSymbolAddress((void**)&attn, g_attn);
    cudaGetSymbolAddress((void**)&xr,   g_xr);
    cudaGetSymbolAddress((void**)&wqr,  g_wqr);
    cudaGetSymbolAddress((void**)&wkr,  g_wkr);
    cudaGetSymbolAddress((void**)&wvr,  g_wvr);
    cudaGetSymbolAddress((void**)&wor,  g_wor);

    cudaFuncSetAttribute(attn_kernel, cudaFuncAttributeMaxDynamicSharedMemorySize,
                         ATTN_SMEM_BYTES);
    cudaFuncSetAttribute(gemm_tf32_v2, cudaFuncAttributeMaxDynamicSharedMemorySize,
                         GEMM_DYN);

    rope_table_kernel<<<(SEQ * 64 + 255) / 256, 256>>>(pos);

    /* pre-round operands to tf32 (rna) */
    const int NB = 256;
    round_copy_kernel<<<(MROWS*EMB/4 + NB-1)/NB, NB>>>(x,  xr,  MROWS*EMB/4);
    round_copy_kernel<<<(EMB*EMB/4   + NB-1)/NB, NB>>>(wq, wqr, EMB*EMB/4);
    round_copy_kernel<<<(KVE*EMB/4   + NB-1)/NB, NB>>>(wk, wkr, KVE*EMB/4);
    round_copy_kernel<<<(KVE*EMB/4   + NB-1)/NB, NB>>>(wv, wvr, KVE*EMB/4);
    round_copy_kernel<<<(EMB*EMB/4   + NB-1)/NB, NB>>>(wo, wor, EMB*EMB/4);

    gemm_tf32_v2<<<dim3(EMB / 128, MROWS / 128), 256, GEMM_DYN>>>(xr, wqr, qp, EMB);
    gemm_tf32_v2<<<dim3(KVE / 128, MROWS / 128), 256, GEMM_DYN>>>(xr, wkr, kp, KVE);
    gemm_tf32_v2<<<dim3(KVE / 128, MROWS / 128), 256, GEMM_DYN>>>(xr, wvr, vp, KVE);

    rope_apply_kernel<<<MROWS, 256>>>(qp, NH);
    rope_apply_kernel<<<MROWS, 256>>>(kp, NKV);

    attn_kernel<<<dim3(SEQ / 128, NH, BATCH), 256, ATTN_SMEM_BYTES>>>();

    gemm_tf32_v2<<<dim3(EMB / 128, MROWS / 128), 256, GEMM_DYN>>>(attn, wor, out, EMB);
}

// round 15
// speedup vs baseline: 1.4032x; 1.1772x over previous
#include <cuda_runtime.h>
#include <math.h>
#include <cstdint>

#define BATCH 2
#define SEQ   2048
#define EMB   4096
#define NH    32
#define NKV   8
#define HD    128
#define MROWS (BATCH*SEQ)     /* 4096 */
#define KVE   (NKV*HD)        /* 1024 */
#define GK    4096            /* K dim of every GEMM in this block */

/* ---------------- scratch (allocation-free: __device__ globals) ---------------- */
__device__ float g_qp[(size_t)MROWS*EMB];    /* 64 MB */
__device__ float g_kp[(size_t)MROWS*KVE];    /* 16 MB */
__device__ float g_vp[(size_t)MROWS*KVE];    /* 16 MB */
__device__ float g_attn[(size_t)MROWS*EMB];  /* 64 MB, written tf32-rounded */
__device__ float g_xr[(size_t)MROWS*EMB];    /* 64 MB, tf32-rounded x */
__device__ float g_wqr[(size_t)EMB*EMB];     /* 64 MB */
__device__ float g_wkr[(size_t)KVE*EMB];     /* 16 MB */
__device__ float g_wvr[(size_t)KVE*EMB];     /* 16 MB */
__device__ float g_wor[(size_t)EMB*EMB];     /* 64 MB */
__device__ float g_cos[SEQ*64];
__device__ float g_sin[SEQ*64];

/* ---------------- helpers ---------------- */
__device__ __forceinline__ float tf32r(float x) {
    unsigned u;
    asm("cvt.rna.tf32.f32 %0, %1;" : "=r"(u) : "f"(x));
    return __uint_as_float(u);
}

__device__ __forceinline__ void mma8(float* d, const unsigned* a, const unsigned* b) {
    asm volatile(
        "mma.sync.aligned.m16n8k8.row.col.f32.tf32.tf32.f32 "
        "{%0,%1,%2,%3}, {%4,%5,%6,%7}, {%8,%9}, {%0,%1,%2,%3};\n"
        : "+f"(d[0]), "+f"(d[1]), "+f"(d[2]), "+f"(d[3])
        : "r"(a[0]), "r"(a[1]), "r"(a[2]), "r"(a[3]), "r"(b[0]), "r"(b[1]));
}

__device__ __forceinline__ uint32_t su32(const void* p) {
    uint32_t a;
    asm("{ .reg .u64 t; cvta.to.shared.u64 t, %1; cvt.u32.u64 %0, t; }"
        : "=r"(a) : "l"(p));
    return a;
}

__device__ __forceinline__ void cpa16(uint32_t dst, const void* src) {
    asm volatile("cp.async.cg.shared.global [%0], [%1], 16;"
                 :: "r"(dst), "l"(src) : "memory");
}
#define CP_COMMIT() asm volatile("cp.async.commit_group;" ::: "memory")
#define CP_WAIT2()  asm volatile("cp.async.wait_group 2;"  ::: "memory")

#define LDSM4(r0, r1, r2, r3, addr) \
    asm volatile("ldmatrix.sync.aligned.m8n8.x4.shared.b16 {%0,%1,%2,%3}, [%4];" \
                 : "=r"(r0), "=r"(r1), "=r"(r2), "=r"(r3) : "r"(addr))

/* ---------------- tf32 rounding pass (x + weights) ---------------- */
__global__ void round_copy_kernel(const float* __restrict__ src,
                                  float* __restrict__ dst, int n4) {
    int i = blockIdx.x * blockDim.x + threadIdx.x;
    if (i >= n4) return;
    float4 v = ((const float4*)src)[i];
    v.x = tf32r(v.x); v.y = tf32r(v.y); v.z = tf32r(v.z); v.w = tf32r(v.w);
    ((float4*)dst)[i] = v;
}

/* ---------------- RoPE cos/sin table ---------------- */
__global__ void rope_table_kernel(const int* __restrict__ pos) {
    int i = blockIdx.x * blockDim.x + threadIdx.x;
    if (i >= SEQ * 64) return;
    int s = i >> 6, d = i & 63;
    float e = (float)d * (1.0f / 64.0f);
    float invf = powf(500000.0f, -e);
    float ang = (float)pos[s] * invf;
    float sv, cv;
    sincosf(ang, &sv, &cv);
    g_cos[i] = cv;
    g_sin[i] = sv;
}

/* ---------------- in-place RoPE over [row][h*128+d] ---------------- */
__global__ void rope_apply_kernel(float* __restrict__ buf, int nh) {
    int row = blockIdx.x;
    int s = row & (SEQ - 1);
    float* p = buf + (size_t)row * nh * HD;
    for (int idx = threadIdx.x; idx < nh * 64; idx += blockDim.x) {
        int h = idx >> 6, d = idx & 63;
        float x1 = p[h * HD + d];
        float x2 = p[h * HD + d + 64];
        float c  = g_cos[s * 64 + d];
        float sn = g_sin[s * 64 + d];
        p[h * HD + d]      = x1 * c - x2 * sn;
        p[h * HD + d + 64] = x2 * c + x1 * sn;
    }
}

/* ================= TF32 GEMM v3: C[M,Ntot] = A[M,4096] * W[Ntot,4096]^T =================
 * Inputs pre-rounded to tf32. CTA tile 128x128, BK=32, 3-stage cp.async pipeline,
 * ldmatrix fragment loads, 8 warps (4M x 2N), 2 CTAs/SM (96KB smem, <=128 regs). */
#define G_STAGE 32768
#define GEMM_DYN (3*G_STAGE)

__device__ __forceinline__ void load_chunk_async(
    const float* __restrict__ A, const float* __restrict__ W,
    int m0, int n0, int kk, uint32_t sstage, int tid)
{
#pragma unroll
    for (int it = 0; it < 8; ++it) {
        int lin = tid + it * 256;
        int r = lin >> 3, c = lin & 7;
        const float* src;
        int off;
        if (it < 4) {
            src = A + (size_t)(m0 + r) * GK + (kk + c * 4);
            off = r * 128 + c * 16;
        } else {
            src = W + (size_t)(n0 + r - 128) * GK + (kk + c * 4);
            off = 16384 + (r - 128) * 128 + c * 16;
        }
        off ^= ((off >> 3) & 0x70);              /* 128B xor swizzle */
        cpa16(sstage + off, src);
    }
}

__global__ void __launch_bounds__(256, 2)
gemm_tf32_v3(const float* __restrict__ A, const float* __restrict__ W,
             float* __restrict__ C, int Ntot)
{
    extern __shared__ char dsm[];
    const uint32_t s0 = su32(dsm);

    const int tid  = threadIdx.x;
    const int lane = tid & 31, warp = tid >> 5;
    const int m0 = blockIdx.y * 128, n0 = blockIdx.x * 128;
    const int wm = (warp >> 1) * 32;
    const int wn = (warp & 1) * 64;
    const int g  = lane >> 2, tg = lane & 3;

    /* per-lane ldmatrix addressing (stage-relative) */
    const uint32_t xorv = (uint32_t)(lane & 7) << 4;
    const uint32_t aOff = (uint32_t)(wm + (lane & 15)) * 128;
    const uint32_t aHi  = (uint32_t)(lane >> 4) * 16;
    const uint32_t bOff = 16384u +
        (uint32_t)(wn + (lane & 7) + ((lane >> 4) & 1) * 8) * 128;
    const uint32_t bHi  = (uint32_t)((lane >> 3) & 1) * 16;

    float acc[2][8][4];
#pragma unroll
    for (int i = 0; i < 2; i++)
#pragma unroll
        for (int j = 0; j < 8; j++)
#pragma unroll
            for (int l = 0; l < 4; l++) acc[i][j][l] = 0.0f;

    /* preload 3 stages */
    load_chunk_async(A, W, m0, n0, 0,  s0,              tid); CP_COMMIT();
    load_chunk_async(A, W, m0, n0, 32, s0 + G_STAGE,    tid); CP_COMMIT();
    load_chunk_async(A, W, m0, n0, 64, s0 + 2*G_STAGE,  tid); CP_COMMIT();

    const int n = GK / 32;                       /* 128 chunks */
    uint32_t slot = 0;                           /* i % 3 */
    for (int i = 0; i < n; ++i) {
        CP_WAIT2();
        __syncthreads();

        const uint32_t sb = s0 + slot * G_STAGE;
#pragma unroll
        for (int ks = 0; ks < 4; ++ks) {
            const uint32_t ka = ((uint32_t)(ks * 32) + aHi) ^ xorv;
            const uint32_t kb = ((uint32_t)(ks * 32) + bHi) ^ xorv;
            unsigned a0[4], a1[4], bf[16];
            LDSM4(a0[0], a0[1], a0[2], a0[3], sb + aOff + ka);
            LDSM4(a1[0], a1[1], a1[2], a1[3], sb + aOff + 2048 + ka);
            LDSM4(bf[0],  bf[1],  bf[2],  bf[3],  sb + bOff + kb);
            LDSM4(bf[4],  bf[5],  bf[6],  bf[7],  sb + bOff + 2048 + kb);
            LDSM4(bf[8],  bf[9],  bf[10], bf[11], sb + bOff + 4096 + kb);
            LDSM4(bf[12], bf[13], bf[14], bf[15], sb + bOff + 6144 + kb);
#pragma unroll
            for (int nt = 0; nt < 8; ++nt) {
                mma8(acc[0][nt], a0, &bf[nt * 2]);
                mma8(acc[1][nt], a1, &bf[nt * 2]);
            }
        }
        __syncthreads();

        if (i + 3 < n)
            load_chunk_async(A, W, m0, n0, (i + 3) * 32, sb, tid);
        CP_COMMIT();

        slot = (slot == 2) ? 0 : slot + 1;
    }

    /* epilogue */
#pragma unroll
    for (int mt = 0; mt < 2; ++mt) {
        int r0 = m0 + wm + mt * 16 + g;
#pragma unroll
        for (int nt = 0; nt < 8; ++nt) {
            int cN = n0 + wn + nt * 8 + 2 * tg;
            *(float2*)(C + (size_t)r0 * Ntot + cN)       = make_float2(acc[mt][nt][0], acc[mt][nt][1]);
            *(float2*)(C + (size_t)(r0 + 8) * Ntot + cN) = make_float2(acc[mt][nt][2], acc[mt][nt][3]);
        }
    }
}

/* ---------------- causal flash attention (GQA), TF32 mma ---------------- */
#define ATTN_SMEM_FLOATS (128*132 + 64*132 + 64*132 + 128*68)
#define ATTN_SMEM_BYTES  (ATTN_SMEM_FLOATS * 4)

__global__ void __launch_bounds__(256, 1) attn_kernel() {
    extern __shared__ float sm[];
    float* Qs = sm;                      /* [128][132] */
    float* Ks = Qs + 128 * 132;          /* [64][132]  */
    float* Vs = Ks + 64 * 132;           /* [64][132]  */
    float* Ps = Vs + 64 * 132;           /* [128][68]  */

    const int tid  = threadIdx.x;
    const int lane = tid & 31, warp = tid >> 5;
    const int g = lane >> 2, tg = lane & 3;
    const int qt = blockIdx.x, h = blockIdx.y, b = blockIdx.z;
    const int q0 = qt * 128;
    const int kvh = h >> 2;

    const float* qbase = g_qp + (size_t)b * SEQ * EMB + (size_t)h * HD;
    const float* kbase = g_kp + (size_t)b * SEQ * KVE + (size_t)kvh * HD;
    const float* vbase = g_vp + (size_t)b * SEQ * KVE + (size_t)kvh * HD;

#pragma unroll
    for (int i = 0; i < 16; i++) {
        int lin = tid + i * 256;
        int r = lin >> 5;
        int c = (lin & 31) << 2;
        float4 v = *(const float4*)(qbase + (size_t)(q0 + r) * EMB + c);
        Qs[r * 132 + c + 0] = tf32r(v.x);
        Qs[r * 132 + c + 1] = tf32r(v.y);
        Qs[r * 132 + c + 2] = tf32r(v.z);
        Qs[r * 132 + c + 3] = tf32r(v.w);
    }

    float o[16][4];
#pragma unroll
    for (int i = 0; i < 16; i++)
#pragma unroll
        for (int j = 0; j < 4; j++) o[i][j] = 0.0f;

    float mi0 = -1e30f, mi1 = -1e30f, li0 = 0.0f, li1 = 0.0f;
    const int rowl0 = warp * 16 + g;
    const float SC = 0.08838834764831845f;
    const int nkt = 2 * qt + 2;

    for (int kt = 0; kt < nkt; ++kt) {
        const int k0 = kt * 64;
        __syncthreads();
#pragma unroll
        for (int i = 0; i < 8; i++) {
            int lin = tid + i * 256;
            int r = lin >> 5;
            int c = (lin & 31) << 2;
            float4 kv4 = *(const float4*)(kbase + (size_t)(k0 + r) * KVE + c);
            Ks[r * 132 + c + 0] = tf32r(kv4.x);
            Ks[r * 132 + c + 1] = tf32r(kv4.y);
            Ks[r * 132 + c + 2] = tf32r(kv4.z);
            Ks[r * 132 + c + 3] = tf32r(kv4.w);
            float4 vv4 = *(const float4*)(vbase + (size_t)(k0 + r) * KVE + c);
            Vs[r * 132 + c + 0] = tf32r(vv4.x);
            Vs[r * 132 + c + 1] = tf32r(vv4.y);
            Vs[r * 132 + c + 2] = tf32r(vv4.z);
            Vs[r * 132 + c + 3] = tf32r(vv4.w);
        }
        __syncthreads();

        float sacc[8][4];
#pragma unroll
        for (int i = 0; i < 8; i++)
#pragma unroll
            for (int j = 0; j < 4; j++) sacc[i][j] = 0.0f;

#pragma unroll
        for (int ks = 0; ks < 16; ++ks) {
            const int k = ks * 8;
            unsigned af[4];
            af[0] = __float_as_uint(Qs[rowl0 * 132 + k + tg]);
            af[1] = __float_as_uint(Qs[(rowl0 + 8) * 132 + k + tg]);
            af[2] = __float_as_uint(Qs[rowl0 * 132 + k + 4 + tg]);
            af[3] = __float_as_uint(Qs[(rowl0 + 8) * 132 + k + 4 + tg]);
#pragma unroll
            for (int nt = 0; nt < 8; ++nt) {
                int cN = nt * 8 + g;
                unsigned bf[2];
                bf[0] = __float_as_uint(Ks[cN * 132 + k + tg]);
                bf[1] = __float_as_uint(Ks[cN * 132 + k + 4 + tg]);
                mma8(sacc[nt], af, bf);
            }
        }

        const int qg0 = q0 + rowl0, qg1 = qg0 + 8;
        float rmax0 = -1e30f, rmax1 = -1e30f;
#pragma unroll
        for (int nt = 0; nt < 8; ++nt) {
            int c0 = k0 + nt * 8 + 2 * tg;
            float v0 = sacc[nt][0] * SC; if (c0     > qg0) v0 = -1e30f;
            float v1 = sacc[nt][1] * SC; if (c0 + 1 > qg0) v1 = -1e30f;
            float v2 = sacc[nt][2] * SC; if (c0     > qg1) v2 = -1e30f;
            float v3 = sacc[nt][3] * SC; if (c0 + 1 > qg1) v3 = -1e30f;
            sacc[nt][0] = v0; sacc[nt][1] = v1; sacc[nt][2] = v2; sacc[nt][3] = v3;
            rmax0 = fmaxf(rmax0, fmaxf(v0, v1));
            rmax1 = fmaxf(rmax1, fmaxf(v2, v3));
        }
#pragma unroll
        for (int off = 1; off < 4; off <<= 1) {
            rmax0 = fmaxf(rmax0, __shfl_xor_sync(0xffffffffu, rmax0, off));
            rmax1 = fmaxf(rmax1, __shfl_xor_sync(0xffffffffu, rmax1, off));
        }
        float mn0 = fmaxf(mi0, rmax0), mn1 = fmaxf(mi1, rmax1);
        float al0 = __expf(mi0 - mn0), al1 = __expf(mi1 - mn1);
        float rs0 = 0.0f, rs1 = 0.0f;
#pragma unroll
        for (int nt = 0; nt < 8; ++nt) {
            float p0 = __expf(sacc[nt][0] - mn0);
            float p1 = __expf(sacc[nt][1] - mn0);
            float p2 = __expf(sacc[nt][2] - mn1);
            float p3 = __expf(sacc[nt][3] - mn1);
            rs0 += p0 + p1;
            rs1 += p2 + p3;
            int c = nt * 8 + 2 * tg;
            *(float2*)&Ps[rowl0 * 68 + c]       = make_float2(tf32r(p0), tf32r(p1));
            *(float2*)&Ps[(rowl0 + 8) * 68 + c] = make_float2(tf32r(p2), tf32r(p3));
        }
#pragma unroll
        for (int off = 1; off < 4; off <<= 1) {
            rs0 += __shfl_xor_sync(0xffffffffu, rs0, off);
            rs1 += __shfl_xor_sync(0xffffffffu, rs1, off);
        }
        li0 = li0 * al0 + rs0;
        li1 = li1 * al1 + rs1;
        mi0 = mn0; mi1 = mn1;
#pragma unroll
        for (int nt = 0; nt < 16; ++nt) {
            o[nt][0] *= al0; o[nt][1] *= al0;
            o[nt][2] *= al1; o[nt][3] *= al1;
        }
        __syncwarp();

#pragma unroll
        for (int ks = 0; ks < 8; ++ks) {
            const int k = ks * 8;
            unsigned af[4];
            af[0] = __float_as_uint(Ps[rowl0 * 68 + k + tg]);
            af[1] = __float_as_uint(Ps[(rowl0 + 8) * 68 + k + tg]);
            af[2] = __float_as_uint(Ps[rowl0 * 68 + k + 4 + tg]);
            af[3] = __float_as_uint(Ps[(rowl0 + 8) * 68 + k + 4 + tg]);
#pragma unroll
            for (int nt = 0; nt < 16; ++nt) {
                int cN = nt * 8 + g;
                unsigned bf[2];
                bf[0] = __float_as_uint(Vs[(k + tg) * 132 + cN]);
                bf[1] = __float_as_uint(Vs[(k + 4 + tg) * 132 + cN]);
                mma8(o[nt], af, bf);
            }
        }
    }

    /* epilogue: normalize + tf32-round (feeds O-proj as pre-rounded A) */
    float inv0 = 1.0f / li0, inv1 = 1.0f / li1;
    float* obase = g_attn + (size_t)b * SEQ * EMB + (size_t)h * HD;
#pragma unroll
    for (int nt = 0; nt < 16; ++nt) {
        int d = nt * 8 + 2 * tg;
        *(float2*)(obase + (size_t)(q0 + rowl0) * EMB + d) =
            make_float2(tf32r(o[nt][0] * inv0), tf32r(o[nt][1] * inv0));
        *(float2*)(obase + (size_t)(q0 + rowl0 + 8) * EMB + d) =
            make_float2(tf32r(o[nt][2] * inv1), tf32r(o[nt][3] * inv1));
    }
}

/* ---------------- launch ---------------- */
extern "C" void kernel_launch(void* const* d_in, const int* in_sizes, int n_in,
                              void* d_out, int out_size)
{
    (void)in_sizes; (void)n_in; (void)out_size;
    const float* x   = (const float*)d_in[0];
    const float* wq  = (const float*)d_in[1];
    const float* wk  = (const float*)d_in[2];
    const float* wv  = (const float*)d_in[3];
    const float* wo  = (const float*)d_in[4];
    const int*   pos = (const int*)d_in[5];
    float* out = (float*)d_out;

    float *qp, *kp, *vp, *attn, *xr, *wqr, *wkr, *wvr, *wor;
    cudaGetSymbolAddress((void**)&qp,   g_qp);
    cudaGetSymbolAddress((void**)&kp,   g_kp);
    cudaGetSymbolAddress((void**)&vp,   g_vp);
    cudaGetSymbolAddress((void**)&attn, g_attn);
    cudaGetSymbolAddress((void**)&xr,   g_xr);
    cudaGetSymbolAddress((void**)&wqr,  g_wqr);
    cudaGetSymbolAddress((void**)&wkr,  g_wkr);
    cudaGetSymbolAddress((void**)&wvr,  g_wvr);
    cudaGetSymbolAddress((void**)&wor,  g_wor);

    cudaFuncSetAttribute(attn_kernel, cudaFuncAttributeMaxDynamicSharedMemorySize,
                         ATTN_SMEM_BYTES);
    cudaFuncSetAttribute(gemm_tf32_v3, cudaFuncAttributeMaxDynamicSharedMemorySize,
                         GEMM_DYN);

    /* launch order chosen so ncu's "-s 5 -c 1" lands on the Q-proj GEMM (6th launch) */
    const int NB = 256;
    round_copy_kernel<<<(MROWS*EMB/4 + NB-1)/NB, NB>>>(x,  xr,  MROWS*EMB/4);
    round_copy_kernel<<<(EMB*EMB/4   + NB-1)/NB, NB>>>(wq, wqr, EMB*EMB/4);
    round_copy_kernel<<<(KVE*EMB/4   + NB-1)/NB, NB>>>(wk, wkr, KVE*EMB/4);
    round_copy_kernel<<<(KVE*EMB/4   + NB-1)/NB, NB>>>(wv, wvr, KVE*EMB/4);
    round_copy_kernel<<<(EMB*EMB/4   + NB-1)/NB, NB>>>(wo, wor, EMB*EMB/4);

    gemm_tf32_v3<<<dim3(EMB / 128, MROWS / 128), 256, GEMM_DYN>>>(xr, wqr, qp, EMB);
    gemm_tf32_v3<<<dim3(KVE / 128, MROWS / 128), 256, GEMM_DYN>>>(xr, wkr, kp, KVE);
    gemm_tf32_v3<<<dim3(KVE / 128, MROWS / 128), 256, GEMM_DYN>>>(xr, wvr, vp, KVE);

    rope_table_kernel<<<(SEQ * 64 + 255) / 256, 256>>>(pos);
    rope_apply_kernel<<<MROWS, 256>>>(qp, NH);
    rope_apply_kernel<<<MROWS, 256>>>(kp, NKV);

    attn_kernel<<<dim3(SEQ / 128, NH, BATCH), 256, ATTN_SMEM_BYTES>>>();

    gemm_tf32_v3<<<dim3(EMB / 128, MROWS / 128), 256, GEMM_DYN>>>(attn, wor, out, EMB);
}

// round 16
// speedup vs baseline: 1.5400x; 1.0976x over previous
#include <cuda_runtime.h>
#include <math.h>
#include <cstdint>

#define BATCH 2
#define SEQ   2048
#define EMB   4096
#define NH    32
#define NKV   8
#define HD    128
#define MROWS (BATCH*SEQ)     /* 4096 */
#define KVE   (NKV*HD)        /* 1024 */
#define GK    4096            /* K dim of every GEMM in this block */

/* ---------------- scratch (allocation-free: __device__ globals) ---------------- */
__device__ float g_qp[(size_t)MROWS*EMB];    /* 64 MB, tf32-rounded after rope */
__device__ float g_kp[(size_t)MROWS*KVE];    /* 16 MB, tf32-rounded after rope */
__device__ float g_vt[(size_t)BATCH*KVE*SEQ];/* 16 MB, V transposed [b][d][s], rounded */
__device__ float g_attn[(size_t)MROWS*EMB];  /* 64 MB, tf32-rounded */
__device__ float g_xr[(size_t)MROWS*EMB];    /* 64 MB, tf32-rounded x */
__device__ float g_wqr[(size_t)EMB*EMB];     /* 64 MB */
__device__ float g_wkr[(size_t)KVE*EMB];     /* 16 MB */
__device__ float g_wvr[(size_t)KVE*EMB];     /* 16 MB */
__device__ float g_wor[(size_t)EMB*EMB];     /* 64 MB */
__device__ float g_cos[SEQ*64];
__device__ float g_sin[SEQ*64];

/* ---------------- helpers ---------------- */
__device__ __forceinline__ float tf32r(float x) {
    unsigned u;
    asm("cvt.rna.tf32.f32 %0, %1;" : "=r"(u) : "f"(x));
    return __uint_as_float(u);
}

__device__ __forceinline__ void mma8(float* d, const unsigned* a, const unsigned* b) {
    asm volatile(
        "mma.sync.aligned.m16n8k8.row.col.f32.tf32.tf32.f32 "
        "{%0,%1,%2,%3}, {%4,%5,%6,%7}, {%8,%9}, {%0,%1,%2,%3};\n"
        : "+f"(d[0]), "+f"(d[1]), "+f"(d[2]), "+f"(d[3])
        : "r"(a[0]), "r"(a[1]), "r"(a[2]), "r"(a[3]), "r"(b[0]), "r"(b[1]));
}

__device__ __forceinline__ uint32_t su32(const void* p) {
    uint32_t a;
    asm("{ .reg .u64 t; cvta.to.shared.u64 t, %1; cvt.u32.u64 %0, t; }"
        : "=r"(a) : "l"(p));
    return a;
}

__device__ __forceinline__ void cpa16(uint32_t dst, const void* src) {
    asm volatile("cp.async.cg.shared.global [%0], [%1], 16;"
                 :: "r"(dst), "l"(src) : "memory");
}
#define CP_COMMIT() asm volatile("cp.async.commit_group;" ::: "memory")
#define CP_WAIT2()  asm volatile("cp.async.wait_group 2;"  ::: "memory")
#define CP_WAIT0()  asm volatile("cp.async.wait_group 0;"  ::: "memory")

#define LDSM4(r0, r1, r2, r3, addr) \
    asm volatile("ldmatrix.sync.aligned.m8n8.x4.shared.b16 {%0,%1,%2,%3}, [%4];" \
                 : "=r"(r0), "=r"(r1), "=r"(r2), "=r"(r3) : "r"(addr))

/* ---------------- tf32 rounding pass (x + weights) ---------------- */
__global__ void round_copy_kernel(const float* __restrict__ src,
                                  float* __restrict__ dst, int n4) {
    int i = blockIdx.x * blockDim.x + threadIdx.x;
    if (i >= n4) return;
    float4 v = ((const float4*)src)[i];
    v.x = tf32r(v.x); v.y = tf32r(v.y); v.z = tf32r(v.z); v.w = tf32r(v.w);
    ((float4*)dst)[i] = v;
}

/* ---------------- RoPE cos/sin table ---------------- */
__global__ void rope_table_kernel(const int* __restrict__ pos) {
    int i = blockIdx.x * blockDim.x + threadIdx.x;
    if (i >= SEQ * 64) return;
    int s = i >> 6, d = i & 63;
    float e = (float)d * (1.0f / 64.0f);
    float invf = powf(500000.0f, -e);
    float ang = (float)pos[s] * invf;
    float sv, cv;
    sincosf(ang, &sv, &cv);
    g_cos[i] = cv;
    g_sin[i] = sv;
}

/* -------- in-place RoPE over [row][h*128+d]; writes tf32-rounded values -------- */
__global__ void rope_apply_kernel(float* __restrict__ buf, int nh) {
    int row = blockIdx.x;
    int s = row & (SEQ - 1);
    float* p = buf + (size_t)row * nh * HD;
    for (int idx = threadIdx.x; idx < nh * 64; idx += blockDim.x) {
        int h = idx >> 6, d = idx & 63;
        float x1 = p[h * HD + d];
        float x2 = p[h * HD + d + 64];
        float c  = g_cos[s * 64 + d];
        float sn = g_sin[s * 64 + d];
        p[h * HD + d]      = tf32r(x1 * c - x2 * sn);
        p[h * HD + d + 64] = tf32r(x2 * c + x1 * sn);
    }
}

/* ================= TF32 GEMM v3: C[M,Ntot] = A[M,4096] * W[Ntot,4096]^T =================
 * TR=false: normal row-major C.  TR=true: writes C transposed+tf32-rounded into
 * g_vt layout [b][col][s] (used for the V projection).                              */
#define G_STAGE 32768
#define GEMM_DYN (3*G_STAGE)

__device__ __forceinline__ void load_chunk_async(
    const float* __restrict__ A, const float* __restrict__ W,
    int m0, int n0, int kk, uint32_t sstage, int tid)
{
#pragma unroll
    for (int it = 0; it < 8; ++it) {
        int lin = tid + it * 256;
        int r = lin >> 3, c = lin & 7;
        const float* src;
        int off;
        if (it < 4) {
            src = A + (size_t)(m0 + r) * GK + (kk + c * 4);
            off = r * 128 + c * 16;
        } else {
            src = W + (size_t)(n0 + r - 128) * GK + (kk + c * 4);
            off = 16384 + (r - 128) * 128 + c * 16;
        }
        off ^= ((off >> 3) & 0x70);              /* 128B xor swizzle */
        cpa16(sstage + off, src);
    }
}

template <bool TR>
__global__ void __launch_bounds__(256, 2)
gemm_tf32_v3(const float* __restrict__ A, const float* __restrict__ W,
             float* __restrict__ C, int Ntot)
{
    extern __shared__ char dsm[];
    const uint32_t s0 = su32(dsm);

    const int tid  = threadIdx.x;
    const int lane = tid & 31, warp = tid >> 5;
    const int m0 = blockIdx.y * 128, n0 = blockIdx.x * 128;
    const int wm = (warp >> 1) * 32;
    const int wn = (warp & 1) * 64;
    const int g  = lane >> 2, tg = lane & 3;

    const uint32_t xorv = (uint32_t)(lane & 7) << 4;
    const uint32_t aOff = (uint32_t)(wm + (lane & 15)) * 128;
    const uint32_t aHi  = (uint32_t)(lane >> 4) * 16;
    const uint32_t bOff = 16384u +
        (uint32_t)(wn + (lane & 7) + ((lane >> 4) & 1) * 8) * 128;
    const uint32_t bHi  = (uint32_t)((lane >> 3) & 1) * 16;

    float acc[2][8][4];
#pragma unroll
    for (int i = 0; i < 2; i++)
#pragma unroll
        for (int j = 0; j < 8; j++)
#pragma unroll
            for (int l = 0; l < 4; l++) acc[i][j][l] = 0.0f;

    load_chunk_async(A, W, m0, n0, 0,  s0,              tid); CP_COMMIT();
    load_chunk_async(A, W, m0, n0, 32, s0 + G_STAGE,    tid); CP_COMMIT();
    load_chunk_async(A, W, m0, n0, 64, s0 + 2*G_STAGE,  tid); CP_COMMIT();

    const int n = GK / 32;
    uint32_t slot = 0;
    for (int i = 0; i < n; ++i) {
        CP_WAIT2();
        __syncthreads();

        const uint32_t sb = s0 + slot * G_STAGE;
#pragma unroll
        for (int ks = 0; ks < 4; ++ks) {
            const uint32_t ka = ((uint32_t)(ks * 32) + aHi) ^ xorv;
            const uint32_t kb = ((uint32_t)(ks * 32) + bHi) ^ xorv;
            unsigned a0[4], a1[4], bf[16];
            LDSM4(a0[0], a0[1], a0[2], a0[3], sb + aOff + ka);
            LDSM4(a1[0], a1[1], a1[2], a1[3], sb + aOff + 2048 + ka);
            LDSM4(bf[0],  bf[1],  bf[2],  bf[3],  sb + bOff + kb);
            LDSM4(bf[4],  bf[5],  bf[6],  bf[7],  sb + bOff + 2048 + kb);
            LDSM4(bf[8],  bf[9],  bf[10], bf[11], sb + bOff + 4096 + kb);
            LDSM4(bf[12], bf[13], bf[14], bf[15], sb + bOff + 6144 + kb);
#pragma unroll
            for (int nt = 0; nt < 8; ++nt) {
                mma8(acc[0][nt], a0, &bf[nt * 2]);
                mma8(acc[1][nt], a1, &bf[nt * 2]);
            }
        }
        __syncthreads();

        if (i + 3 < n)
            load_chunk_async(A, W, m0, n0, (i + 3) * 32, sb, tid);
        CP_COMMIT();

        slot = (slot == 2) ? 0 : slot + 1;
    }

#pragma unroll
    for (int mt = 0; mt < 2; ++mt) {
        int r0 = m0 + wm + mt * 16 + g;
#pragma unroll
        for (int nt = 0; nt < 8; ++nt) {
            int cN = n0 + wn + nt * 8 + 2 * tg;
            if (!TR) {
                *(float2*)(C + (size_t)r0 * Ntot + cN)       = make_float2(acc[mt][nt][0], acc[mt][nt][1]);
                *(float2*)(C + (size_t)(r0 + 8) * Ntot + cN) = make_float2(acc[mt][nt][2], acc[mt][nt][3]);
            } else {
                /* C^T into g_vt[(b*KVE + c)*SEQ + s], tf32-rounded */
                size_t b0 = (size_t)(r0 >> 11) * KVE;
                int s_lo = r0 & 2047;
                C[(b0 + cN    ) * SEQ + s_lo]     = tf32r(acc[mt][nt][0]);
                C[(b0 + cN + 1) * SEQ + s_lo]     = tf32r(acc[mt][nt][1]);
                C[(b0 + cN    ) * SEQ + s_lo + 8] = tf32r(acc[mt][nt][2]);
                C[(b0 + cN + 1) * SEQ + s_lo + 8] = tf32r(acc[mt][nt][3]);
            }
        }
    }
}

/* ============= causal flash attention v2: cp.async + ldmatrix, GQA =============
 * smem (all 128B-atom chunks, xor-swizzled, offsets relative to dyn base):
 *   Q  [128 q][128 d]  : 4 chunks x 16384            @ 0      (64KB)
 *   K  double buf      : 4 chunks x 8192  per buf    @ 65536  (2x32KB)
 *   Vt double buf      : 2 chunks x 16384 per buf    @ 131072 (2x32KB)
 *   P  [128 q][64 kv]  : 2 chunks x 16384            @ 196608 (32KB)    */
#define AT_Q 0
#define AT_K 65536
#define AT_V 131072
#define AT_P 196608
#define ATTN_DYN 229376

__device__ __forceinline__ void attn_load_kv(
    const float* __restrict__ kbase, const float* __restrict__ vtbase,
    int k0, uint32_t s0, uint32_t kbuf_rel, uint32_t vbuf_rel, int tid)
{
#pragma unroll
    for (int it = 0; it < 8; ++it) {            /* K tile: 64 rows x 128 floats */
        int lin = tid + it * 256;
        int r = lin >> 5, c = lin & 31;
        uint32_t off = kbuf_rel + (uint32_t)(c >> 3) * 8192 + (uint32_t)r * 128 + (c & 7) * 16;
        off ^= ((off >> 3) & 0x70);
        cpa16(s0 + off, kbase + (size_t)(k0 + r) * KVE + c * 4);
    }
#pragma unroll
    for (int it = 0; it < 8; ++it) {            /* Vt tile: 128 d-rows x 64 kv */
        int lin = tid + it * 256;
        int d = lin >> 4, c = lin & 15;
        uint32_t off = vbuf_rel + (uint32_t)(c >> 3) * 16384 + (uint32_t)d * 128 + (c & 7) * 16;
        off ^= ((off >> 3) & 0x70);
        cpa16(s0 + off, vtbase + (size_t)d * SEQ + k0 + c * 4);
    }
}

__global__ void __launch_bounds__(256, 1) attn_v2() {
    extern __shared__ char smr[];
    const uint32_t s0 = su32(smr);

    const int tid  = threadIdx.x;
    const int lane = tid & 31, warp = tid >> 5;
    const int g = lane >> 2, tg = lane & 3;
    const int qt = blockIdx.x, h = blockIdx.y, b = blockIdx.z;
    const int q0 = qt * 128;
    const int kvh = h >> 2;

    const float* qbase  = g_qp + (size_t)b * SEQ * EMB + (size_t)h * HD;
    const float* kbase  = g_kp + (size_t)b * SEQ * KVE + (size_t)kvh * HD;
    const float* vtbase = g_vt + ((size_t)b * KVE + (size_t)kvh * HD) * SEQ;

    /* Q tile: 128 rows x 128 floats, cp.async (already tf32-rounded) */
#pragma unroll
    for (int it = 0; it < 16; ++it) {
        int lin = tid + it * 256;
        int r = lin >> 5, c = lin & 31;
        uint32_t off = AT_Q + (uint32_t)(c >> 3) * 16384 + (uint32_t)r * 128 + (c & 7) * 16;
        off ^= ((off >> 3) & 0x70);
        cpa16(s0 + off, qbase + (size_t)(q0 + r) * EMB + c * 4);
    }
    attn_load_kv(kbase, vtbase, 0, s0, AT_K, AT_V, tid);
    CP_COMMIT();
    CP_WAIT0();
    __syncthreads();

    /* fragment addressing (same scheme as the GEMM) */
    const uint32_t xorv = (uint32_t)(lane & 7) << 4;
    const uint32_t aHi  = (uint32_t)(lane >> 4) * 16;
    const uint32_t aOff = (uint32_t)(warp * 16 + (lane & 15)) * 128;
    const uint32_t bOff = (uint32_t)((lane & 7) + ((lane >> 4) & 1) * 8) * 128;
    const uint32_t bHi  = (uint32_t)((lane >> 3) & 1) * 16;

    float o[16][4];
#pragma unroll
    for (int i = 0; i < 16; i++)
#pragma unroll
        for (int j = 0; j < 4; j++) o[i][j] = 0.0f;

    float mi0 = -1e30f, mi1 = -1e30f, li0 = 0.0f, li1 = 0.0f;
    const int rowl0 = warp * 16 + g;
    const float SC = 0.08838834764831845f;   /* 1/sqrt(128) */
    const int nkt = 2 * qt + 2;

    for (int kt = 0; kt < nkt; ++kt) {
        const int k0 = kt * 64;
        const uint32_t kbuf = AT_K + (uint32_t)(kt & 1) * 32768;
        const uint32_t vbuf = AT_V + (uint32_t)(kt & 1) * 32768;

        if (kt + 1 < nkt)
            attn_load_kv(kbase, vtbase, (kt + 1) * 64, s0,
                         AT_K + (uint32_t)((kt + 1) & 1) * 32768,
                         AT_V + (uint32_t)((kt + 1) & 1) * 32768, tid);
        CP_COMMIT();

        /* ---- S = Q K^T (16 q x 64 kv per warp) ---- */
        float sacc[8][4];
#pragma unroll
        for (int i = 0; i < 8; i++)
#pragma unroll
            for (int j = 0; j < 4; j++) sacc[i][j] = 0.0f;

#pragma unroll
        for (int ks = 0; ks < 16; ++ks) {
            const uint32_t ka = ((uint32_t)((ks & 3) * 32) + aHi) ^ xorv;
            const uint32_t kb = ((uint32_t)((ks & 3) * 32) + bHi) ^ xorv;
            unsigned af[4], kf[4];
            LDSM4(af[0], af[1], af[2], af[3],
                  s0 + AT_Q + (uint32_t)(ks >> 2) * 16384 + aOff + ka);
            const uint32_t kbs = s0 + kbuf + (uint32_t)(ks >> 2) * 8192 + bOff + kb;
#pragma unroll
            for (int nt = 0; nt < 4; ++nt) {
                LDSM4(kf[0], kf[1], kf[2], kf[3], kbs + (uint32_t)nt * 2048);
                mma8(sacc[nt * 2],     af, kf);
                mma8(sacc[nt * 2 + 1], af, kf + 2);
            }
        }

        /* ---- scale + causal mask + online softmax ---- */
        const int qg0 = q0 + rowl0, qg1 = qg0 + 8;
        float rmax0 = -1e30f, rmax1 = -1e30f;
#pragma unroll
        for (int nt = 0; nt < 8; ++nt) {
            int c0 = k0 + nt * 8 + 2 * tg;
            float v0 = sacc[nt][0] * SC; if (c0     > qg0) v0 = -1e30f;
            float v1 = sacc[nt][1] * SC; if (c0 + 1 > qg0) v1 = -1e30f;
            float v2 = sacc[nt][2] * SC; if (c0     > qg1) v2 = -1e30f;
            float v3 = sacc[nt][3] * SC; if (c0 + 1 > qg1) v3 = -1e30f;
            sacc[nt][0] = v0; sacc[nt][1] = v1; sacc[nt][2] = v2; sacc[nt][3] = v3;
            rmax0 = fmaxf(rmax0, fmaxf(v0, v1));
            rmax1 = fmaxf(rmax1, fmaxf(v2, v3));
        }
#pragma unroll
        for (int off = 1; off < 4; off <<= 1) {
            rmax0 = fmaxf(rmax0, __shfl_xor_sync(0xffffffffu, rmax0, off));
            rmax1 = fmaxf(rmax1, __shfl_xor_sync(0xffffffffu, rmax1, off));
        }
        float mn0 = fmaxf(mi0, rmax0), mn1 = fmaxf(mi1, rmax1);
        float al0 = __expf(mi0 - mn0), al1 = __expf(mi1 - mn1);
        float rs0 = 0.0f, rs1 = 0.0f;
#pragma unroll
        for (int nt = 0; nt < 8; ++nt) {
            float p0 = __expf(sacc[nt][0] - mn0);
            float p1 = __expf(sacc[nt][1] - mn0);
            float p2 = __expf(sacc[nt][2] - mn1);
            float p3 = __expf(sacc[nt][3] - mn1);
            rs0 += p0 + p1;
            rs1 += p2 + p3;
            int c = nt * 8 + 2 * tg;
            uint32_t o0 = AT_P + (uint32_t)(c >> 5) * 16384 + (uint32_t)rowl0 * 128 + (c & 31) * 4;
            o0 ^= ((o0 >> 3) & 0x70);
            *(float2*)(smr + o0) = make_float2(tf32r(p0), tf32r(p1));
            uint32_t o1 = AT_P + (uint32_t)(c >> 5) * 16384 + (uint32_t)(rowl0 + 8) * 128 + (c & 31) * 4;
            o1 ^= ((o1 >> 3) & 0x70);
            *(float2*)(smr + o1) = make_float2(tf32r(p2), tf32r(p3));
        }
#pragma unroll
        for (int off = 1; off < 4; off <<= 1) {
            rs0 += __shfl_xor_sync(0xffffffffu, rs0, off);
            rs1 += __shfl_xor_sync(0xffffffffu, rs1, off);
        }
        li0 = li0 * al0 + rs0;
        li1 = li1 * al1 + rs1;
        mi0 = mn0; mi1 = mn1;
#pragma unroll
        for (int nt = 0; nt < 16; ++nt) {
            o[nt][0] *= al0; o[nt][1] *= al0;
            o[nt][2] *= al1; o[nt][3] *= al1;
        }
        __syncwarp();

        /* ---- O += P Vt (16 q x 128 d per warp) ---- */
#pragma unroll
        for (int ks = 0; ks < 8; ++ks) {
            const uint32_t ka = ((uint32_t)((ks & 3) * 32) + aHi) ^ xorv;
            const uint32_t kb = ((uint32_t)((ks & 3) * 32) + bHi) ^ xorv;
            unsigned pf[4], vf[4];
            LDSM4(pf[0], pf[1], pf[2], pf[3],
                  s0 + AT_P + (uint32_t)(ks >> 2) * 16384 + aOff + ka);
            const uint32_t vbs = s0 + vbuf + (uint32_t)(ks >> 2) * 16384 + bOff + kb;
#pragma unroll
            for (int nt = 0; nt < 8; ++nt) {
                LDSM4(vf[0], vf[1], vf[2], vf[3], vbs + (uint32_t)nt * 2048);
                mma8(o[nt * 2],     pf, vf);
                mma8(o[nt * 2 + 1], pf, vf + 2);
            }
        }

        CP_WAIT0();
        __syncthreads();
    }

    /* epilogue: normalize + tf32-round (feeds O-proj as pre-rounded A) */
    float inv0 = 1.0f / li0, inv1 = 1.0f / li1;
    float* obase = g_attn + (size_t)b * SEQ * EMB + (size_t)h * HD;
#pragma unroll
    for (int nt = 0; nt < 16; ++nt) {
        int d = nt * 8 + 2 * tg;
        *(float2*)(obase + (size_t)(q0 + rowl0) * EMB + d) =
            make_float2(tf32r(o[nt][0] * inv0), tf32r(o[nt][1] * inv0));
        *(float2*)(obase + (size_t)(q0 + rowl0 + 8) * EMB + d) =
            make_float2(tf32r(o[nt][2] * inv1), tf32r(o[nt][3] * inv1));
    }
}

/* ---------------- launch ---------------- */
extern "C" void kernel_launch(void* const* d_in, const int* in_sizes, int n_in,
                              void* d_out, int out_size)
{
    (void)in_sizes; (void)n_in; (void)out_size;
    const float* x   = (const float*)d_in[0];
    const float* wq  = (const float*)d_in[1];
    const float* wk  = (const float*)d_in[2];
    const float* wv  = (const float*)d_in[3];
    const float* wo  = (const float*)d_in[4];
    const int*   pos = (const int*)d_in[5];
    float* out = (float*)d_out;

    float *qp, *kp, *vt, *attn, *xr, *wqr, *wkr, *wvr, *wor;
    cudaGetSymbolAddress((void**)&qp,   g_qp);
    cudaGetSymbolAddress((void**)&kp,   g_kp);
    cudaGetSymbolAddress((void**)&vt,   g_vt);
    cudaGetSymbolAddress((void**)&attn, g_attn);
    cudaGetSymbolAddress((void**)&xr,   g_xr);
    cudaGetSymbolAddress((void**)&wqr,  g_wqr);
    cudaGetSymbolAddress((void**)&wkr,  g_wkr);
    cudaGetSymbolAddress((void**)&wvr,  g_wvr);
    cudaGetSymbolAddress((void**)&wor,  g_wor);

    cudaFuncSetAttribute(attn_v2, cudaFuncAttributeMaxDynamicSharedMemorySize,
                         ATTN_DYN);
    cudaFuncSetAttribute(gemm_tf32_v3<false>,
                         cudaFuncAttributeMaxDynamicSharedMemorySize, GEMM_DYN);
    cudaFuncSetAttribute(gemm_tf32_v3<true>,
                         cudaFuncAttributeMaxDynamicSharedMemorySize, GEMM_DYN);

    const int NB = 256;
    round_copy_kernel<<<(MROWS*EMB/4 + NB-1)/NB, NB>>>(x,  xr,  MROWS*EMB/4);
    round_copy_kernel<<<(EMB*EMB/4   + NB-1)/NB, NB>>>(wq, wqr, EMB*EMB/4);
    round_copy_kernel<<<(KVE*EMB/4   + NB-1)/NB, NB>>>(wk, wkr, KVE*EMB/4);

    /* Q-proj early so a "-s 5" profile has a chance to land on it */
    gemm_tf32_v3<false><<<dim3(EMB / 128, MROWS / 128), 256, GEMM_DYN>>>(xr, wqr, qp, EMB);

    round_copy_kernel<<<(KVE*EMB/4 + NB-1)/NB, NB>>>(wv, wvr, KVE*EMB/4);
    round_copy_kernel<<<(EMB*EMB/4 + NB-1)/NB, NB>>>(wo, wor, EMB*EMB/4);

    gemm_tf32_v3<false><<<dim3(KVE / 128, MROWS / 128), 256, GEMM_DYN>>>(xr, wkr, kp, KVE);
    gemm_tf32_v3<true ><<<dim3(KVE / 128, MROWS / 128), 256, GEMM_DYN>>>(xr, wvr, vt, KVE);

    rope_table_kernel<<<(SEQ * 64 + 255) / 256, 256>>>(pos);
    rope_apply_kernel<<<MROWS, 256>>>(qp, NH);
    rope_apply_kernel<<<MROWS, 256>>>(kp, NKV);

    attn_v2<<<dim3(SEQ / 128, NH, BATCH), 256, ATTN_DYN>>>();

    gemm_tf32_v3<false><<<dim3(EMB / 128, MROWS / 128), 256, GEMM_DYN>>>(attn, wor, out, EMB);
}

// round 17
// speedup vs baseline: 1.5454x; 1.0035x over previous
#include <cuda_runtime.h>
#include <math.h>
#include <cstdint>

#define BATCH 2
#define SEQ   2048
#define EMB   4096
#define NH    32
#define NKV   8
#define HD    128
#define MROWS (BATCH*SEQ)     /* 4096 */
#define KVE   (NKV*HD)        /* 1024 */
#define GK    4096            /* K dim of every GEMM in this block */

/* ---------------- scratch (allocation-free: __device__ globals) ---------------- */
__device__ float g_qp[(size_t)MROWS*EMB];    /* 64 MB, tf32-rounded after rope */
__device__ float g_kp[(size_t)MROWS*KVE];    /* 16 MB, tf32-rounded after rope */
__device__ float g_vt[(size_t)BATCH*KVE*SEQ];/* 16 MB, V transposed [b][d][s], rounded */
__device__ float g_attn[(size_t)MROWS*EMB];  /* 64 MB, tf32-rounded */
__device__ float g_xr[(size_t)MROWS*EMB];    /* 64 MB, tf32-rounded x */
__device__ float g_wqr[(size_t)EMB*EMB];     /* 64 MB */
__device__ float g_wkr[(size_t)KVE*EMB];     /* 16 MB */
__device__ float g_wvr[(size_t)KVE*EMB];     /* 16 MB */
__device__ float g_wor[(size_t)EMB*EMB];     /* 64 MB */
__device__ float g_cos[SEQ*64];
__device__ float g_sin[SEQ*64];

/* ---------------- helpers ---------------- */
__device__ __forceinline__ float tf32r(float x) {
    unsigned u;
    asm("cvt.rna.tf32.f32 %0, %1;" : "=r"(u) : "f"(x));
    return __uint_as_float(u);
}

__device__ __forceinline__ void mma8(float* d, const unsigned* a, const unsigned* b) {
    asm volatile(
        "mma.sync.aligned.m16n8k8.row.col.f32.tf32.tf32.f32 "
        "{%0,%1,%2,%3}, {%4,%5,%6,%7}, {%8,%9}, {%0,%1,%2,%3};\n"
        : "+f"(d[0]), "+f"(d[1]), "+f"(d[2]), "+f"(d[3])
        : "r"(a[0]), "r"(a[1]), "r"(a[2]), "r"(a[3]), "r"(b[0]), "r"(b[1]));
}

__device__ __forceinline__ uint32_t su32(const void* p) {
    uint32_t a;
    asm("{ .reg .u64 t; cvta.to.shared.u64 t, %1; cvt.u32.u64 %0, t; }"
        : "=r"(a) : "l"(p));
    return a;
}

__device__ __forceinline__ void cpa16(uint32_t dst, const void* src) {
    asm volatile("cp.async.cg.shared.global [%0], [%1], 16;"
                 :: "r"(dst), "l"(src) : "memory");
}
#define CP_COMMIT() asm volatile("cp.async.commit_group;" ::: "memory")
#define CP_WAIT1()  asm volatile("cp.async.wait_group 1;"  ::: "memory")
#define CP_WAIT0()  asm volatile("cp.async.wait_group 0;"  ::: "memory")

#define LDSM4(r0, r1, r2, r3, addr) \
    asm volatile("ldmatrix.sync.aligned.m8n8.x4.shared.b16 {%0,%1,%2,%3}, [%4];" \
                 : "=r"(r0), "=r"(r1), "=r"(r2), "=r"(r3) : "r"(addr))

/* ---------------- tf32 rounding pass (x + weights) ---------------- */
__global__ void round_copy_kernel(const float* __restrict__ src,
                                  float* __restrict__ dst, int n4) {
    int i = blockIdx.x * blockDim.x + threadIdx.x;
    if (i >= n4) return;
    float4 v = ((const float4*)src)[i];
    v.x = tf32r(v.x); v.y = tf32r(v.y); v.z = tf32r(v.z); v.w = tf32r(v.w);
    ((float4*)dst)[i] = v;
}

/* ---------------- RoPE cos/sin table ---------------- */
__global__ void rope_table_kernel(const int* __restrict__ pos) {
    int i = blockIdx.x * blockDim.x + threadIdx.x;
    if (i >= SEQ * 64) return;
    int s = i >> 6, d = i & 63;
    float e = (float)d * (1.0f / 64.0f);
    float invf = powf(500000.0f, -e);
    float ang = (float)pos[s] * invf;
    float sv, cv;
    sincosf(ang, &sv, &cv);
    g_cos[i] = cv;
    g_sin[i] = sv;
}

/* -------- in-place RoPE over [row][h*128+d]; writes tf32-rounded values -------- */
__global__ void rope_apply_kernel(float* __restrict__ buf, int nh) {
    int row = blockIdx.x;
    int s = row & (SEQ - 1);
    float* p = buf + (size_t)row * nh * HD;
    for (int idx = threadIdx.x; idx < nh * 64; idx += blockDim.x) {
        int h = idx >> 6, d = idx & 63;
        float x1 = p[h * HD + d];
        float x2 = p[h * HD + d + 64];
        float c  = g_cos[s * 64 + d];
        float sn = g_sin[s * 64 + d];
        p[h * HD + d]      = tf32r(x1 * c - x2 * sn);
        p[h * HD + d + 64] = tf32r(x2 * c + x1 * sn);
    }
}

/* ================= TF32 GEMM v4: C[M,Ntot] = A[M,4096] * W[Ntot,4096]^T =================
 * Single-sync 3-stage cp.async rotation:
 *   preload slots 0,1; wait_group 1; sync
 *   iter i: refill slot (i+2)%3 -> compute slot i%3 -> wait_group 1 -> sync
 * Invariant: entering iter i, cp.async groups <= i are complete.
 * TR=true writes C transposed+rounded into g_vt (V projection).                    */
#define G_STAGE 32768
#define GEMM_DYN (3*G_STAGE)

__device__ __forceinline__ void load_chunk_async(
    const float* __restrict__ A, const float* __restrict__ W,
    int m0, int n0, int kk, uint32_t sstage, int tid)
{
#pragma unroll
    for (int it = 0; it < 8; ++it) {
        int lin = tid + it * 256;
        int r = lin >> 3, c = lin & 7;
        const float* src;
        int off;
        if (it < 4) {
            src = A + (size_t)(m0 + r) * GK + (kk + c * 4);
            off = r * 128 + c * 16;
        } else {
            src = W + (size_t)(n0 + r - 128) * GK + (kk + c * 4);
            off = 16384 + (r - 128) * 128 + c * 16;
        }
        off ^= ((off >> 3) & 0x70);              /* 128B xor swizzle */
        cpa16(sstage + off, src);
    }
}

template <bool TR>
__global__ void __launch_bounds__(256, 2)
gemm_tf32_v4(const float* __restrict__ A, const float* __restrict__ W,
             float* __restrict__ C, int Ntot)
{
    extern __shared__ char dsm[];
    const uint32_t s0 = su32(dsm);

    const int tid  = threadIdx.x;
    const int lane = tid & 31, warp = tid >> 5;
    const int m0 = blockIdx.y * 128, n0 = blockIdx.x * 128;
    const int wm = (warp >> 1) * 32;
    const int wn = (warp & 1) * 64;
    const int g  = lane >> 2, tg = lane & 3;

    const uint32_t xorv = (uint32_t)(lane & 7) << 4;
    const uint32_t aOff = (uint32_t)(wm + (lane & 15)) * 128;
    const uint32_t aHi  = (uint32_t)(lane >> 4) * 16;
    const uint32_t bOff = 16384u +
        (uint32_t)(wn + (lane & 7) + ((lane >> 4) & 1) * 8) * 128;
    const uint32_t bHi  = (uint32_t)((lane >> 3) & 1) * 16;

    float acc[2][8][4];
#pragma unroll
    for (int i = 0; i < 2; i++)
#pragma unroll
        for (int j = 0; j < 8; j++)
#pragma unroll
            for (int l = 0; l < 4; l++) acc[i][j][l] = 0.0f;

    /* preload slots 0,1 */
    load_chunk_async(A, W, m0, n0, 0,  s0,           tid); CP_COMMIT();
    load_chunk_async(A, W, m0, n0, 32, s0 + G_STAGE, tid); CP_COMMIT();
    CP_WAIT1();
    __syncthreads();

    const int n = GK / 32;                       /* 128 chunks */
    uint32_t slot = 0;                           /* i % 3 */
    uint32_t rslot = 2;                          /* (i+2) % 3 */
    for (int i = 0; i < n; ++i) {
        /* refill (issued before compute so it overlaps the mma stream) */
        if (i + 2 < n)
            load_chunk_async(A, W, m0, n0, (i + 2) * 32, s0 + rslot * G_STAGE, tid);
        CP_COMMIT();

        /* compute slot i%3 (group i complete by invariant) */
        const uint32_t sb = s0 + slot * G_STAGE;
#pragma unroll
        for (int ks = 0; ks < 4; ++ks) {
            const uint32_t ka = ((uint32_t)(ks * 32) + aHi) ^ xorv;
            const uint32_t kb = ((uint32_t)(ks * 32) + bHi) ^ xorv;
            unsigned a0[4], a1[4], bf[16];
            LDSM4(a0[0], a0[1], a0[2], a0[3], sb + aOff + ka);
            LDSM4(a1[0], a1[1], a1[2], a1[3], sb + aOff + 2048 + ka);
            LDSM4(bf[0],  bf[1],  bf[2],  bf[3],  sb + bOff + kb);
            LDSM4(bf[4],  bf[5],  bf[6],  bf[7],  sb + bOff + 2048 + kb);
            LDSM4(bf[8],  bf[9],  bf[10], bf[11], sb + bOff + 4096 + kb);
            LDSM4(bf[12], bf[13], bf[14], bf[15], sb + bOff + 6144 + kb);
#pragma unroll
            for (int nt = 0; nt < 8; ++nt) {
                mma8(acc[0][nt], a0, &bf[nt * 2]);
                mma8(acc[1][nt], a1, &bf[nt * 2]);
            }
        }

        CP_WAIT1();                              /* group i+1 complete */
        __syncthreads();                         /* visibility + slot-reuse safety */

        slot  = (slot  == 2) ? 0 : slot  + 1;
        rslot = (rslot == 2) ? 0 : rslot + 1;
    }

#pragma unroll
    for (int mt = 0; mt < 2; ++mt) {
        int r0 = m0 + wm + mt * 16 + g;
#pragma unroll
        for (int nt = 0; nt < 8; ++nt) {
            int cN = n0 + wn + nt * 8 + 2 * tg;
            if (!TR) {
                *(float2*)(C + (size_t)r0 * Ntot + cN)       = make_float2(acc[mt][nt][0], acc[mt][nt][1]);
                *(float2*)(C + (size_t)(r0 + 8) * Ntot + cN) = make_float2(acc[mt][nt][2], acc[mt][nt][3]);
            } else {
                /* C^T into g_vt[(b*KVE + c)*SEQ + s], tf32-rounded */
                size_t b0 = (size_t)(r0 >> 11) * KVE;
                int s_lo = r0 & 2047;
                C[(b0 + cN    ) * SEQ + s_lo]     = tf32r(acc[mt][nt][0]);
                C[(b0 + cN + 1) * SEQ + s_lo]     = tf32r(acc[mt][nt][1]);
                C[(b0 + cN    ) * SEQ + s_lo + 8] = tf32r(acc[mt][nt][2]);
                C[(b0 + cN + 1) * SEQ + s_lo + 8] = tf32r(acc[mt][nt][3]);
            }
        }
    }
}

/* ============= causal flash attention v2: cp.async + ldmatrix, GQA =============
 * smem layout (128B-atom chunks, xor-swizzled, offsets from dyn base):
 *   Q 64KB @0, K dbl 2x32KB @65536, Vt dbl 2x32KB @131072, P 32KB @196608 */
#define AT_Q 0
#define AT_K 65536
#define AT_V 131072
#define AT_P 196608
#define ATTN_DYN 229376

__device__ __forceinline__ void attn_load_kv(
    const float* __restrict__ kbase, const float* __restrict__ vtbase,
    int k0, uint32_t s0, uint32_t kbuf_rel, uint32_t vbuf_rel, int tid)
{
#pragma unroll
    for (int it = 0; it < 8; ++it) {            /* K tile: 64 rows x 128 floats */
        int lin = tid + it * 256;
        int r = lin >> 5, c = lin & 31;
        uint32_t off = kbuf_rel + (uint32_t)(c >> 3) * 8192 + (uint32_t)r * 128 + (c & 7) * 16;
        off ^= ((off >> 3) & 0x70);
        cpa16(s0 + off, kbase + (size_t)(k0 + r) * KVE + c * 4);
    }
#pragma unroll
    for (int it = 0; it < 8; ++it) {            /* Vt tile: 128 d-rows x 64 kv */
        int lin = tid + it * 256;
        int d = lin >> 4, c = lin & 15;
        uint32_t off = vbuf_rel + (uint32_t)(c >> 3) * 16384 + (uint32_t)d * 128 + (c & 7) * 16;
        off ^= ((off >> 3) & 0x70);
        cpa16(s0 + off, vtbase + (size_t)d * SEQ + k0 + c * 4);
    }
}

__global__ void __launch_bounds__(256, 1) attn_v2() {
    extern __shared__ char smr[];
    const uint32_t s0 = su32(smr);

    const int tid  = threadIdx.x;
    const int lane = tid & 31, warp = tid >> 5;
    const int g = lane >> 2, tg = lane & 3;
    const int qt = blockIdx.x, h = blockIdx.y, b = blockIdx.z;
    const int q0 = qt * 128;
    const int kvh = h >> 2;

    const float* qbase  = g_qp + (size_t)b * SEQ * EMB + (size_t)h * HD;
    const float* kbase  = g_kp + (size_t)b * SEQ * KVE + (size_t)kvh * HD;
    const float* vtbase = g_vt + ((size_t)b * KVE + (size_t)kvh * HD) * SEQ;

#pragma unroll
    for (int it = 0; it < 16; ++it) {
        int lin = tid + it * 256;
        int r = lin >> 5, c = lin & 31;
        uint32_t off = AT_Q + (uint32_t)(c >> 3) * 16384 + (uint32_t)r * 128 + (c & 7) * 16;
        off ^= ((off >> 3) & 0x70);
        cpa16(s0 + off, qbase + (size_t)(q0 + r) * EMB + c * 4);
    }
    attn_load_kv(kbase, vtbase, 0, s0, AT_K, AT_V, tid);
    CP_COMMIT();
    CP_WAIT0();
    __syncthreads();

    const uint32_t xorv = (uint32_t)(lane & 7) << 4;
    const uint32_t aHi  = (uint32_t)(lane >> 4) * 16;
    const uint32_t aOff = (uint32_t)(warp * 16 + (lane & 15)) * 128;
    const uint32_t bOff = (uint32_t)((lane & 7) + ((lane >> 4) & 1) * 8) * 128;
    const uint32_t bHi  = (uint32_t)((lane >> 3) & 1) * 16;

    float o[16][4];
#pragma unroll
    for (int i = 0; i < 16; i++)
#pragma unroll
        for (int j = 0; j < 4; j++) o[i][j] = 0.0f;

    float mi0 = -1e30f, mi1 = -1e30f, li0 = 0.0f, li1 = 0.0f;
    const int rowl0 = warp * 16 + g;
    const float SC = 0.08838834764831845f;   /* 1/sqrt(128) */
    const int nkt = 2 * qt + 2;

    for (int kt = 0; kt < nkt; ++kt) {
        const int k0 = kt * 64;
        const uint32_t kbuf = AT_K + (uint32_t)(kt & 1) * 32768;
        const uint32_t vbuf = AT_V + (uint32_t)(kt & 1) * 32768;

        if (kt + 1 < nkt)
            attn_load_kv(kbase, vtbase, (kt + 1) * 64, s0,
                         AT_K + (uint32_t)((kt + 1) & 1) * 32768,
                         AT_V + (uint32_t)((kt + 1) & 1) * 32768, tid);
        CP_COMMIT();

        /* ---- S = Q K^T (16 q x 64 kv per warp) ---- */
        float sacc[8][4];
#pragma unroll
        for (int i = 0; i < 8; i++)
#pragma unroll
            for (int j = 0; j < 4; j++) sacc[i][j] = 0.0f;

#pragma unroll
        for (int ks = 0; ks < 16; ++ks) {
            const uint32_t ka = ((uint32_t)((ks & 3) * 32) + aHi) ^ xorv;
            const uint32_t kb = ((uint32_t)((ks & 3) * 32) + bHi) ^ xorv;
            unsigned af[4], kf[4];
            LDSM4(af[0], af[1], af[2], af[3],
                  s0 + AT_Q + (uint32_t)(ks >> 2) * 16384 + aOff + ka);
            const uint32_t kbs = s0 + kbuf + (uint32_t)(ks >> 2) * 8192 + bOff + kb;
#pragma unroll
            for (int nt = 0; nt < 4; ++nt) {
                LDSM4(kf[0], kf[1], kf[2], kf[3], kbs + (uint32_t)nt * 2048);
                mma8(sacc[nt * 2],     af, kf);
                mma8(sacc[nt * 2 + 1], af, kf + 2);
            }
        }

        /* ---- scale + causal mask + online softmax ---- */
        const int qg0 = q0 + rowl0, qg1 = qg0 + 8;
        float rmax0 = -1e30f, rmax1 = -1e30f;
#pragma unroll
        for (int nt = 0; nt < 8; ++nt) {
            int c0 = k0 + nt * 8 + 2 * tg;
            float v0 = sacc[nt][0] * SC; if (c0     > qg0) v0 = -1e30f;
            float v1 = sacc[nt][1] * SC; if (c0 + 1 > qg0) v1 = -1e30f;
            float v2 = sacc[nt][2] * SC; if (c0     > qg1) v2 = -1e30f;
            float v3 = sacc[nt][3] * SC; if (c0 + 1 > qg1) v3 = -1e30f;
            sacc[nt][0] = v0; sacc[nt][1] = v1; sacc[nt][2] = v2; sacc[nt][3] = v3;
            rmax0 = fmaxf(rmax0, fmaxf(v0, v1));
            rmax1 = fmaxf(rmax1, fmaxf(v2, v3));
        }
#pragma unroll
        for (int off = 1; off < 4; off <<= 1) {
            rmax0 = fmaxf(rmax0, __shfl_xor_sync(0xffffffffu, rmax0, off));
            rmax1 = fmaxf(rmax1, __shfl_xor_sync(0xffffffffu, rmax1, off));
        }
        float mn0 = fmaxf(mi0, rmax0), mn1 = fmaxf(mi1, rmax1);
        float al0 = __expf(mi0 - mn0), al1 = __expf(mi1 - mn1);
        float rs0 = 0.0f, rs1 = 0.0f;
#pragma unroll
        for (int nt = 0; nt < 8; ++nt) {
            float p0 = __expf(sacc[nt][0] - mn0);
            float p1 = __expf(sacc[nt][1] - mn0);
            float p2 = __expf(sacc[nt][2] - mn1);
            float p3 = __expf(sacc[nt][3] - mn1);
            rs0 += p0 + p1;
            rs1 += p2 + p3;
            int c = nt * 8 + 2 * tg;
            uint32_t o0 = AT_P + (uint32_t)(c >> 5) * 16384 + (uint32_t)rowl0 * 128 + (c & 31) * 4;
            o0 ^= ((o0 >> 3) & 0x70);
            *(float2*)(smr + o0) = make_float2(tf32r(p0), tf32r(p1));
            uint32_t o1 = AT_P + (uint32_t)(c >> 5) * 16384 + (uint32_t)(rowl0 + 8) * 128 + (c & 31) * 4;
            o1 ^= ((o1 >> 3) & 0x70);
            *(float2*)(smr + o1) = make_float2(tf32r(p2), tf32r(p3));
        }
#pragma unroll
        for (int off = 1; off < 4; off <<= 1) {
            rs0 += __shfl_xor_sync(0xffffffffu, rs0, off);
            rs1 += __shfl_xor_sync(0xffffffffu, rs1, off);
        }
        li0 = li0 * al0 + rs0;
        li1 = li1 * al1 + rs1;
        mi0 = mn0; mi1 = mn1;
#pragma unroll
        for (int nt = 0; nt < 16; ++nt) {
            o[nt][0] *= al0; o[nt][1] *= al0;
            o[nt][2] *= al1; o[nt][3] *= al1;
        }
        __syncwarp();

        /* ---- O += P Vt (16 q x 128 d per warp) ---- */
#pragma unroll
        for (int ks = 0; ks < 8; ++ks) {
            const uint32_t ka = ((uint32_t)((ks & 3) * 32) + aHi) ^ xorv;
            const uint32_t kb = ((uint32_t)((ks & 3) * 32) + bHi) ^ xorv;
            unsigned pf[4], vf[4];
            LDSM4(pf[0], pf[1], pf[2], pf[3],
                  s0 + AT_P + (uint32_t)(ks >> 2) * 16384 + aOff + ka);
            const uint32_t vbs = s0 + vbuf + (uint32_t)(ks >> 2) * 16384 + bOff + kb;
#pragma unroll
            for (int nt = 0; nt < 8; ++nt) {
                LDSM4(vf[0], vf[1], vf[2], vf[3], vbs + (uint32_t)nt * 2048);
                mma8(o[nt * 2],     pf, vf);
                mma8(o[nt * 2 + 1], pf, vf + 2);
            }
        }

        CP_WAIT0();
        __syncthreads();
    }

    /* epilogue: normalize + tf32-round (feeds O-proj as pre-rounded A) */
    float inv0 = 1.0f / li0, inv1 = 1.0f / li1;
    float* obase = g_attn + (size_t)b * SEQ * EMB + (size_t)h * HD;
#pragma unroll
    for (int nt = 0; nt < 16; ++nt) {
        int d = nt * 8 + 2 * tg;
        *(float2*)(obase + (size_t)(q0 + rowl0) * EMB + d) =
            make_float2(tf32r(o[nt][0] * inv0), tf32r(o[nt][1] * inv0));
        *(float2*)(obase + (size_t)(q0 + rowl0 + 8) * EMB + d) =
            make_float2(tf32r(o[nt][2] * inv1), tf32r(o[nt][3] * inv1));
    }
}

/* ---------------- launch ---------------- */
extern "C" void kernel_launch(void* const* d_in, const int* in_sizes, int n_in,
                              void* d_out, int out_size)
{
    (void)in_sizes; (void)n_in; (void)out_size;
    const float* x   = (const float*)d_in[0];
    const float* wq  = (const float*)d_in[1];
    const float* wk  = (const float*)d_in[2];
    const float* wv  = (const float*)d_in[3];
    const float* wo  = (const float*)d_in[4];
    const int*   pos = (const int*)d_in[5];
    float* out = (float*)d_out;

    float *qp, *kp, *vt, *attn, *xr, *wqr, *wkr, *wvr, *wor;
    cudaGetSymbolAddress((void**)&qp,   g_qp);
    cudaGetSymbolAddress((void**)&kp,   g_kp);
    cudaGetSymbolAddress((void**)&vt,   g_vt);
    cudaGetSymbolAddress((void**)&attn, g_attn);
    cudaGetSymbolAddress((void**)&xr,   g_xr);
    cudaGetSymbolAddress((void**)&wqr,  g_wqr);
    cudaGetSymbolAddress((void**)&wkr,  g_wkr);
    cudaGetSymbolAddress((void**)&wvr,  g_wvr);
    cudaGetSymbolAddress((void**)&wor,  g_wor);

    cudaFuncSetAttribute(attn_v2, cudaFuncAttributeMaxDynamicSharedMemorySize,
                         ATTN_DYN);
    cudaFuncSetAttribute(gemm_tf32_v4<false>,
                         cudaFuncAttributeMaxDynamicSharedMemorySize, GEMM_DYN);
    cudaFuncSetAttribute(gemm_tf32_v4<true>,
                         cudaFuncAttributeMaxDynamicSharedMemorySize, GEMM_DYN);

    const int NB = 256;
    round_copy_kernel<<<(MROWS*EMB/4 + NB-1)/NB, NB>>>(x,  xr,  MROWS*EMB/4);
    round_copy_kernel<<<(EMB*EMB/4   + NB-1)/NB, NB>>>(wq, wqr, EMB*EMB/4);
    round_copy_kernel<<<(KVE*EMB/4   + NB-1)/NB, NB>>>(wk, wkr, KVE*EMB/4);

    /* Q-proj at launch slot 4 (profiler "-s 5" lands here) */
    gemm_tf32_v4<false><<<dim3(EMB / 128, MROWS / 128), 256, GEMM_DYN>>>(xr, wqr, qp, EMB);

    round_copy_kernel<<<(KVE*EMB/4 + NB-1)/NB, NB>>>(wv, wvr, KVE*EMB/4);
    round_copy_kernel<<<(EMB*EMB/4 + NB-1)/NB, NB>>>(wo, wor, EMB*EMB/4);

    gemm_tf32_v4<false><<<dim3(KVE / 128, MROWS / 128), 256, GEMM_DYN>>>(xr, wkr, kp, KVE);
    gemm_tf32_v4<true ><<<dim3(KVE / 128, MROWS / 128), 256, GEMM_DYN>>>(xr, wvr, vt, KVE);

    rope_table_kernel<<<(SEQ * 64 + 255) / 256, 256>>>(pos);
    rope_apply_kernel<<<MROWS, 256>>>(qp, NH);
    rope_apply_kernel<<<MROWS, 256>>>(kp, NKV);

    attn_v2<<<dim3(SEQ / 128, NH, BATCH), 256, ATTN_DYN>>>();

    gemm_tf32_v4<false><<<dim3(EMB / 128, MROWS / 128), 256, GEMM_DYN>>>(attn, wor, out, EMB);
}